// round 2
// baseline (speedup 1.0000x reference)
#include <cuda_runtime.h>
#include <math.h>

#define HIDDEN  128
#define N_NODES 50000
#define N_EDGES 600000
#define LN_EPS  1e-5f

// Scratch (static device arrays: no allocation allowed)
__device__ float g_A[N_NODES * 3 * HIDDEN];   // per-node src-side typed projections
__device__ float g_B[N_NODES * 3 * HIDDEN];   // per-node dst-side typed projections
__device__ float g_agg[N_NODES * HIDDEN];     // atomic accumulator -> normalized agg
__device__ int   g_cnt[N_NODES * 4];          // per-node per-type edge counts (stride 4)

// ---------------- zero scratch ----------------
__global__ void k_zero() {
    int i = blockIdx.x * blockDim.x + threadIdx.x;
    int stride = gridDim.x * blockDim.x;
    for (int j = i; j < N_NODES * HIDDEN; j += stride) g_agg[j] = 0.f;
    for (int j = i; j < N_NODES * 4; j += stride) g_cnt[j] = 0;
}

// ---------------- projection GEMM: x[N,128] @ Wcomb[128,768] -> g_A, g_B ----------------
// Output column j in [0,768): j<384 -> A[n][t= j/128][h=j%128], else B with jj=j-384.
// Block: 128 rows x 64 cols, 256 threads, each thread 8x4 outputs.
__global__ void k_proj(const float* __restrict__ x, const float* __restrict__ Wmsg) {
    extern __shared__ float sm[];
    float* xs = sm;                // [128][128]
    float* ws = sm + 128 * 128;    // [128][64]  (k-major)
    const int tid = threadIdx.x;
    const int n0 = blockIdx.x * 128;
    const int j0 = blockIdx.y * 64;

    // load x tile (coalesced float4)
    const float4* x4 = (const float4*)x;
    for (int i = tid; i < 4096; i += 256) {          // 128*32 float4
        int m = i >> 5, k4 = i & 31;
        float4 v = make_float4(0.f, 0.f, 0.f, 0.f);
        int n = n0 + m;
        if (n < N_NODES) v = x4[n * 32 + k4];
        ((float4*)xs)[i] = v;
    }
    // load W tile: ws[c][j-j0] = Wmsg[t][part*128 + c][h]
    for (int i = tid; i < 2048; i += 256) {          // 128*16 float4
        int c = i >> 4, j4 = i & 15;
        int j = j0 + j4 * 4;
        int part = (j >= 384) ? 1 : 0;
        int jj = j - part * 384;
        int t = jj >> 7, h = jj & 127;
        ((float4*)ws)[i] = *(const float4*)(Wmsg + ((t * 256 + part * 128 + c) * 128 + h));
    }
    __syncthreads();

    const int tx = tid & 15;   // 16 col-groups * 4 cols
    const int ty = tid >> 4;   // 16 row-groups * 8 rows
    float acc[8][4];
#pragma unroll
    for (int r = 0; r < 8; r++)
#pragma unroll
        for (int c = 0; c < 4; c++) acc[r][c] = 0.f;

    const float* xrow = xs + (ty * 8) * 128;
#pragma unroll 4
    for (int k = 0; k < 128; k++) {
        float4 b = *(const float4*)(ws + k * 64 + tx * 4);
#pragma unroll
        for (int r = 0; r < 8; r++) {
            float a = xrow[r * 128 + k];
            acc[r][0] += a * b.x;
            acc[r][1] += a * b.y;
            acc[r][2] += a * b.z;
            acc[r][3] += a * b.w;
        }
    }

    int part = (j0 >= 384) ? 1 : 0;
    float* outp = part ? g_B : g_A;
    int jj0 = j0 - part * 384 + tx * 4;
#pragma unroll
    for (int r = 0; r < 8; r++) {
        int n = n0 + ty * 8 + r;
        if (n >= N_NODES) break;
        float4 v = make_float4(acc[r][0], acc[r][1], acc[r][2], acc[r][3]);
        *(float4*)(outp + n * 384 + jj0) = v;
    }
}

// ---------------- per-(dst,type) histogram ----------------
__global__ void k_hist(const int* __restrict__ ei, const int* __restrict__ et) {
    int e = blockIdx.x * blockDim.x + threadIdx.x;
    if (e >= N_EDGES) return;
    int dst = ei[N_EDGES + e];
    int t = et[e];
    atomicAdd(&g_cnt[dst * 4 + t], 1);
}

// ---------------- edge scatter: agg[dst] += A[src, t]  (one warp per edge) ----------------
__global__ void k_scatter(const int* __restrict__ ei, const int* __restrict__ et) {
    int w = (blockIdx.x * blockDim.x + threadIdx.x) >> 5;
    if (w >= N_EDGES) return;
    int lane = threadIdx.x & 31;
    int src = ei[w];
    int dst = ei[N_EDGES + w];
    int t = et[w];
    float4 v = *(const float4*)(g_A + (src * 3 + t) * HIDDEN + lane * 4);
    float* p = g_agg + dst * HIDDEN + lane * 4;
    asm volatile("red.global.add.v4.f32 [%0], {%1,%2,%3,%4};"
                 :: "l"(p), "f"(v.x), "f"(v.y), "f"(v.z), "f"(v.w)
                 : "memory");
}

// ---------------- finalize: add count-weighted B terms + bias, normalize by degree ----------------
__global__ void k_finalize(const float* __restrict__ bmsg) {
    int idx = blockIdx.x * blockDim.x + threadIdx.x;
    if (idx >= N_NODES * HIDDEN) return;
    int n = idx >> 7, c = idx & 127;
    int c0 = g_cnt[n * 4 + 0];
    int c1 = g_cnt[n * 4 + 1];
    int c2 = g_cnt[n * 4 + 2];
    float v = g_agg[idx]
            + (float)c0 * (g_B[(n * 3 + 0) * HIDDEN + c] + bmsg[c])
            + (float)c1 * (g_B[(n * 3 + 1) * HIDDEN + c] + bmsg[HIDDEN + c])
            + (float)c2 * (g_B[(n * 3 + 2) * HIDDEN + c] + bmsg[2 * HIDDEN + c]);
    float tot = (float)(c0 + c1 + c2);
    g_agg[idx] = v / fmaxf(tot, 1.f);
}

// ---------------- update GEMM [x|agg][N,256] @ Wupd[256,128] + fused LN/GELU/residual ----------------
// Block: 64 rows x 128 cols, 256 threads: tx=tid&31 (4 cols), ty=tid>>5 (8 rows).
// Each warp owns 8 full output rows -> shfl reduction for LayerNorm.
__global__ void k_update(const float* __restrict__ x, const float* __restrict__ Wupd,
                         const float* __restrict__ bupd, const float* __restrict__ gamma,
                         const float* __restrict__ beta, float* __restrict__ out) {
    extern __shared__ float sm[];
    float* is = sm;                // [64][256]
    float* ws = sm + 64 * 256;     // [256][128] (k-major)
    const int tid = threadIdx.x;
    const int n0 = blockIdx.x * 64;

    // input tile: cols 0..127 = x, 128..255 = agg
    for (int i = tid; i < 4096; i += 256) {          // 64*64 float4
        int m = i >> 6, k4 = i & 63;
        float4 v = make_float4(0.f, 0.f, 0.f, 0.f);
        int n = n0 + m;
        if (n < N_NODES) {
            if (k4 < 32) v = ((const float4*)x)[n * 32 + k4];
            else         v = ((const float4*)g_agg)[n * 32 + (k4 - 32)];
        }
        ((float4*)is)[i] = v;
    }
    // W tile (already k-major [256][128])
    for (int i = tid; i < 8192; i += 256) {
        ((float4*)ws)[i] = ((const float4*)Wupd)[i];
    }
    __syncthreads();

    const int tx = tid & 31;
    const int ty = tid >> 5;
    float acc[8][4];
#pragma unroll
    for (int r = 0; r < 8; r++)
#pragma unroll
        for (int c = 0; c < 4; c++) acc[r][c] = 0.f;

    const float* irow = is + (ty * 8) * 256;
#pragma unroll 2
    for (int k = 0; k < 256; k++) {
        float4 b = *(const float4*)(ws + k * 128 + tx * 4);
#pragma unroll
        for (int r = 0; r < 8; r++) {
            float a = irow[r * 256 + k];
            acc[r][0] += a * b.x;
            acc[r][1] += a * b.y;
            acc[r][2] += a * b.z;
            acc[r][3] += a * b.w;
        }
    }

    float4 bb = *(const float4*)(bupd + tx * 4);
    float4 gg = *(const float4*)(gamma + tx * 4);
    float4 be = *(const float4*)(beta + tx * 4);
    const float inv_h = 1.f / 128.f;
    const float inv_sqrt2 = 0.70710678118654752f;

#pragma unroll
    for (int r = 0; r < 8; r++) {
        int n = n0 + ty * 8 + r;
        float h0 = acc[r][0] + bb.x;
        float h1 = acc[r][1] + bb.y;
        float h2 = acc[r][2] + bb.z;
        float h3 = acc[r][3] + bb.w;
        float s  = h0 + h1 + h2 + h3;
        float sq = h0 * h0 + h1 * h1 + h2 * h2 + h3 * h3;
#pragma unroll
        for (int o = 16; o > 0; o >>= 1) {
            s  += __shfl_xor_sync(0xffffffffu, s, o);
            sq += __shfl_xor_sync(0xffffffffu, sq, o);
        }
        float mu = s * inv_h;
        float var = sq * inv_h - mu * mu;
        float rs = rsqrtf(var + LN_EPS);
        if (n < N_NODES) {
            float4 xv = ((const float4*)x)[n * 32 + tx];
            float hn, ge;
            float4 o;
            hn = (h0 - mu) * rs * gg.x + be.x;
            ge = 0.5f * hn * (1.f + erff(hn * inv_sqrt2));
            o.x = xv.x + ge;
            hn = (h1 - mu) * rs * gg.y + be.y;
            ge = 0.5f * hn * (1.f + erff(hn * inv_sqrt2));
            o.y = xv.y + ge;
            hn = (h2 - mu) * rs * gg.z + be.z;
            ge = 0.5f * hn * (1.f + erff(hn * inv_sqrt2));
            o.z = xv.z + ge;
            hn = (h3 - mu) * rs * gg.w + be.w;
            ge = 0.5f * hn * (1.f + erff(hn * inv_sqrt2));
            o.w = xv.w + ge;
            ((float4*)out)[n * 32 + tx] = o;
        }
    }
}

extern "C" void kernel_launch(void* const* d_in, const int* in_sizes, int n_in,
                              void* d_out, int out_size) {
    const float* x     = (const float*)d_in[0];
    const int*   ei    = (const int*)d_in[1];   // edge_index [2, E] (int32 after jax canonicalization)
    const int*   et    = (const int*)d_in[2];   // edge_type [E]
    const float* Wmsg  = (const float*)d_in[3];
    const float* bmsg  = (const float*)d_in[4];
    const float* Wupd  = (const float*)d_in[5];
    const float* bupd  = (const float*)d_in[6];
    const float* gamma = (const float*)d_in[7];
    const float* beta  = (const float*)d_in[8];
    float* out = (float*)d_out;

    // opt-in to large dynamic smem (idempotent; safe during capture)
    cudaFuncSetAttribute(k_proj,   cudaFuncAttributeMaxDynamicSharedMemorySize, 96 * 1024);
    cudaFuncSetAttribute(k_update, cudaFuncAttributeMaxDynamicSharedMemorySize, 192 * 1024);

    k_zero<<<512, 256>>>();

    dim3 gproj((N_NODES + 127) / 128, 12);
    k_proj<<<gproj, 256, 96 * 1024>>>(x, Wmsg);

    k_hist<<<(N_EDGES + 255) / 256, 256>>>(ei, et);

    long long sthreads = (long long)N_EDGES * 32;
    k_scatter<<<(unsigned)((sthreads + 255) / 256), 256>>>(ei, et);

    k_finalize<<<(N_NODES * HIDDEN + 255) / 256, 256>>>(bmsg);

    k_update<<<(N_NODES + 63) / 64, 256, 192 * 1024>>>(x, Wupd, bupd, gamma, beta, out);
}

// round 3
// speedup vs baseline: 1.4760x; 1.4760x over previous
#include <cuda_runtime.h>
#include <math.h>
#include <stdint.h>

#define HIDDEN  128
#define N_NODES 50000
#define N_EDGES 600000
#define LN_EPS  1e-5f
#define TPAD    132   // smem row stride (floats): bank = (4*row + col) % 32 -> conflict-free frags

// Scratch (static device arrays: no allocation allowed)
__device__ float g_A[N_NODES * 3 * HIDDEN];   // per-node src-side typed projections
__device__ float g_B[N_NODES * 3 * HIDDEN];   // per-node dst-side typed projections
__device__ float g_agg[N_NODES * HIDDEN];     // atomic accumulator -> normalized agg
__device__ int   g_cnt[N_NODES * 4];          // per-node per-type edge counts (stride 4)

__device__ __forceinline__ uint32_t f2tf(float f) {
    uint32_t r;
    asm("cvt.rna.tf32.f32 %0, %1;" : "=r"(r) : "f"(f));
    return r;
}

#define MMA_TF32(c, a, b)                                                        \
    asm volatile(                                                                \
        "mma.sync.aligned.m16n8k8.row.col.f32.tf32.tf32.f32 "                    \
        "{%0,%1,%2,%3},{%4,%5,%6,%7},{%8,%9},{%0,%1,%2,%3};"                     \
        : "+f"((c)[0]), "+f"((c)[1]), "+f"((c)[2]), "+f"((c)[3])                 \
        : "r"((a)[0]), "r"((a)[1]), "r"((a)[2]), "r"((a)[3]),                    \
          "r"((b)[0]), "r"((b)[1]))

// ---------------- zero scratch ----------------
__global__ void k_zero() {
    int i = blockIdx.x * blockDim.x + threadIdx.x;
    int stride = gridDim.x * blockDim.x;
    for (int j = i; j < N_NODES * HIDDEN; j += stride) g_agg[j] = 0.f;
    for (int j = i; j < N_NODES * 4; j += stride) g_cnt[j] = 0;
}

// ---------------- projection GEMM (tf32 tensor): x[N,128] @ Wcomb[128,768] -> g_A, g_B ------------
// Block = 128 rows x 64 cols, 8 warps; warp tile 32x32 (2x4 m16n8 frags), K=128 in one smem load.
__global__ void k_proj(const float* __restrict__ x, const float* __restrict__ Wmsg) {
    extern __shared__ uint32_t smp[];
    uint32_t* As = smp;                 // [128][TPAD] tf32 bits, row = m, col = k
    uint32_t* Ws = smp + 128 * TPAD;    // [64][TPAD]  tf32 bits, row = n, col = k
    const int tid = threadIdx.x;
    const int n0 = blockIdx.x * 128;
    const int j0 = blockIdx.y * 64;

    const float4* x4 = (const float4*)x;
    for (int i = tid; i < 128 * 32; i += 256) {
        int m = i >> 5, k4 = i & 31;
        float4 v = make_float4(0.f, 0.f, 0.f, 0.f);
        int n = n0 + m;
        if (n < N_NODES) v = x4[n * 32 + k4];
        uint32_t* d = As + m * TPAD + k4 * 4;
        d[0] = f2tf(v.x); d[1] = f2tf(v.y); d[2] = f2tf(v.z); d[3] = f2tf(v.w);
    }
    for (int i = tid; i < 128 * 16; i += 256) {   // k x (16 float4 of n)
        int k = i >> 4, j4 = i & 15;
        int j = j0 + j4 * 4;
        int part = (j >= 384) ? 1 : 0;
        int jj = j - part * 384;
        int t = jj >> 7, h = jj & 127;
        float4 v = *(const float4*)(Wmsg + ((t * 256 + part * 128 + k) * 128 + h));
        int jl = j4 * 4;
        Ws[(jl + 0) * TPAD + k] = f2tf(v.x);
        Ws[(jl + 1) * TPAD + k] = f2tf(v.y);
        Ws[(jl + 2) * TPAD + k] = f2tf(v.z);
        Ws[(jl + 3) * TPAD + k] = f2tf(v.w);
    }
    __syncthreads();

    const int w = tid >> 5, lane = tid & 31;
    const int gid = lane >> 2, tig = lane & 3;
    const int m0 = (w & 3) * 32;
    const int nw = (w >> 2) * 32;

    float c[2][4][4];
#pragma unroll
    for (int mt = 0; mt < 2; mt++)
#pragma unroll
        for (int nt = 0; nt < 4; nt++)
#pragma unroll
            for (int q = 0; q < 4; q++) c[mt][nt][q] = 0.f;

#pragma unroll
    for (int ks = 0; ks < 16; ks++) {
        int kb = ks * 8;
        uint32_t a[2][4], b[4][2];
#pragma unroll
        for (int mt = 0; mt < 2; mt++) {
            const uint32_t* ap = As + (m0 + mt * 16 + gid) * TPAD + kb + tig;
            a[mt][0] = ap[0];
            a[mt][1] = ap[8 * TPAD];
            a[mt][2] = ap[4];
            a[mt][3] = ap[8 * TPAD + 4];
        }
#pragma unroll
        for (int nt = 0; nt < 4; nt++) {
            const uint32_t* bp = Ws + (nw + nt * 8 + gid) * TPAD + kb + tig;
            b[nt][0] = bp[0];
            b[nt][1] = bp[4];
        }
#pragma unroll
        for (int mt = 0; mt < 2; mt++)
#pragma unroll
            for (int nt = 0; nt < 4; nt++)
                MMA_TF32(c[mt][nt], a[mt], b[nt]);
    }

    int part = (j0 >= 384) ? 1 : 0;
    float* outp = part ? g_B : g_A;
    int jbase = j0 - part * 384 + nw;
#pragma unroll
    for (int mt = 0; mt < 2; mt++) {
        int r0 = n0 + m0 + mt * 16 + gid;
#pragma unroll
        for (int nt = 0; nt < 4; nt++) {
            int col = jbase + nt * 8 + tig * 2;
            if (r0 < N_NODES)
                *(float2*)(outp + r0 * 384 + col) = make_float2(c[mt][nt][0], c[mt][nt][1]);
            if (r0 + 8 < N_NODES)
                *(float2*)(outp + (r0 + 8) * 384 + col) = make_float2(c[mt][nt][2], c[mt][nt][3]);
        }
    }
}

// ---------------- per-(dst,type) histogram ----------------
__global__ void k_hist(const int* __restrict__ ei, const int* __restrict__ et) {
    int e = blockIdx.x * blockDim.x + threadIdx.x;
    if (e >= N_EDGES) return;
    int dst = ei[N_EDGES + e];
    int t = et[e];
    atomicAdd(&g_cnt[dst * 4 + t], 1);
}

// ---------------- edge scatter: agg[dst] += A[src, t]  (one warp per edge) ----------------
__global__ void k_scatter(const int* __restrict__ ei, const int* __restrict__ et) {
    int w = (blockIdx.x * blockDim.x + threadIdx.x) >> 5;
    if (w >= N_EDGES) return;
    int lane = threadIdx.x & 31;
    int src = ei[w];
    int dst = ei[N_EDGES + w];
    int t = et[w];
    float4 v = *(const float4*)(g_A + (src * 3 + t) * HIDDEN + lane * 4);
    float* p = g_agg + dst * HIDDEN + lane * 4;
    asm volatile("red.global.add.v4.f32 [%0], {%1,%2,%3,%4};"
                 :: "l"(p), "f"(v.x), "f"(v.y), "f"(v.z), "f"(v.w)
                 : "memory");
}

// ---------------- finalize: add count-weighted B terms + bias, normalize by degree ----------------
__global__ void k_finalize(const float* __restrict__ bmsg) {
    int idx = blockIdx.x * blockDim.x + threadIdx.x;
    if (idx >= N_NODES * HIDDEN) return;
    int n = idx >> 7, c = idx & 127;
    int c0 = g_cnt[n * 4 + 0];
    int c1 = g_cnt[n * 4 + 1];
    int c2 = g_cnt[n * 4 + 2];
    float v = g_agg[idx]
            + (float)c0 * (g_B[(n * 3 + 0) * HIDDEN + c] + bmsg[c])
            + (float)c1 * (g_B[(n * 3 + 1) * HIDDEN + c] + bmsg[HIDDEN + c])
            + (float)c2 * (g_B[(n * 3 + 2) * HIDDEN + c] + bmsg[2 * HIDDEN + c]);
    float tot = (float)(c0 + c1 + c2);
    g_agg[idx] = v / fmaxf(tot, 1.f);
}

// ---------------- update GEMM (tf32 tensor) + fused LN/GELU/residual ----------------
// Block = 128 rows x 128 cols (full N), 8 warps; warp tile 16x128 so each warp owns whole
// rows -> LayerNorm reduces within lane-quads (2 shfls). K=256 in two 128-tiles.
__global__ void k_update(const float* __restrict__ x, const float* __restrict__ Wupd,
                         const float* __restrict__ bupd, const float* __restrict__ gamma,
                         const float* __restrict__ beta, float* __restrict__ out) {
    extern __shared__ uint32_t smp[];
    uint32_t* Is  = smp;                 // [128][TPAD] input tile (tf32), row = m, col = k
    uint32_t* Ws2 = smp + 128 * TPAD;    // [128][TPAD] weight tile (tf32), row = n, col = k
    const int tid = threadIdx.x;
    const int n0 = blockIdx.x * 128;
    const int w = tid >> 5, lane = tid & 31;
    const int gid = lane >> 2, tig = lane & 3;
    const int m0 = w * 16;

    float c[16][4];
#pragma unroll
    for (int nt = 0; nt < 16; nt++)
#pragma unroll
        for (int q = 0; q < 4; q++) c[nt][q] = 0.f;

    for (int kt = 0; kt < 2; kt++) {
        for (int i = tid; i < 128 * 32; i += 256) {
            int m = i >> 5, k4 = i & 31;
            float4 v = make_float4(0.f, 0.f, 0.f, 0.f);
            int n = n0 + m;
            if (n < N_NODES)
                v = kt ? ((const float4*)g_agg)[n * 32 + k4]
                       : ((const float4*)x)[n * 32 + k4];
            uint32_t* d = Is + m * TPAD + k4 * 4;
            d[0] = f2tf(v.x); d[1] = f2tf(v.y); d[2] = f2tf(v.z); d[3] = f2tf(v.w);
        }
        for (int i = tid; i < 128 * 32; i += 256) {
            int k = i >> 5, h4 = i & 31;
            float4 v = ((const float4*)Wupd)[(kt * 128 + k) * 32 + h4];
            int h = h4 * 4;
            Ws2[(h + 0) * TPAD + k] = f2tf(v.x);
            Ws2[(h + 1) * TPAD + k] = f2tf(v.y);
            Ws2[(h + 2) * TPAD + k] = f2tf(v.z);
            Ws2[(h + 3) * TPAD + k] = f2tf(v.w);
        }
        __syncthreads();

#pragma unroll
        for (int ks = 0; ks < 16; ks++) {
            int kb = ks * 8;
            uint32_t a[4];
            const uint32_t* ap = Is + (m0 + gid) * TPAD + kb + tig;
            a[0] = ap[0];
            a[1] = ap[8 * TPAD];
            a[2] = ap[4];
            a[3] = ap[8 * TPAD + 4];
#pragma unroll
            for (int nt = 0; nt < 16; nt++) {
                uint32_t b[2];
                const uint32_t* bp = Ws2 + (nt * 8 + gid) * TPAD + kb + tig;
                b[0] = bp[0];
                b[1] = bp[4];
                MMA_TF32(c[nt], a, b);
            }
        }
        __syncthreads();
    }

    // Epilogue: bias + LayerNorm + GELU + residual.
    // Thread holds rows r0 = m0+gid, r1 = r0+8; cols nt*8 + tig*2 (+1).
    const int r0 = n0 + m0 + gid;
    const int r1 = r0 + 8;
    float s0 = 0.f, q0 = 0.f, s1 = 0.f, q1 = 0.f;
#pragma unroll
    for (int nt = 0; nt < 16; nt++) {
        int col = nt * 8 + tig * 2;
        float2 bb = *(const float2*)(bupd + col);
        float h0 = c[nt][0] + bb.x, h1 = c[nt][1] + bb.y;
        float h2 = c[nt][2] + bb.x, h3 = c[nt][3] + bb.y;
        c[nt][0] = h0; c[nt][1] = h1; c[nt][2] = h2; c[nt][3] = h3;
        s0 += h0 + h1; q0 += h0 * h0 + h1 * h1;
        s1 += h2 + h3; q1 += h2 * h2 + h3 * h3;
    }
#pragma unroll
    for (int o = 1; o <= 2; o <<= 1) {
        s0 += __shfl_xor_sync(0xffffffffu, s0, o);
        q0 += __shfl_xor_sync(0xffffffffu, q0, o);
        s1 += __shfl_xor_sync(0xffffffffu, s1, o);
        q1 += __shfl_xor_sync(0xffffffffu, q1, o);
    }
    const float inv_h = 1.f / 128.f;
    float mu0 = s0 * inv_h, var0 = q0 * inv_h - mu0 * mu0;
    float mu1 = s1 * inv_h, var1 = q1 * inv_h - mu1 * mu1;
    float rs0 = rsqrtf(var0 + LN_EPS);
    float rs1 = rsqrtf(var1 + LN_EPS);
    const float inv_sqrt2 = 0.70710678118654752f;

#pragma unroll
    for (int nt = 0; nt < 16; nt++) {
        int col = nt * 8 + tig * 2;
        float2 gg = *(const float2*)(gamma + col);
        float2 be = *(const float2*)(beta + col);
        if (r0 < N_NODES) {
            float2 xv = *(const float2*)(x + r0 * HIDDEN + col);
            float hn0 = (c[nt][0] - mu0) * rs0 * gg.x + be.x;
            float hn1 = (c[nt][1] - mu0) * rs0 * gg.y + be.y;
            float g0 = 0.5f * hn0 * (1.f + erff(hn0 * inv_sqrt2));
            float g1 = 0.5f * hn1 * (1.f + erff(hn1 * inv_sqrt2));
            *(float2*)(out + r0 * HIDDEN + col) = make_float2(xv.x + g0, xv.y + g1);
        }
        if (r1 < N_NODES) {
            float2 xv = *(const float2*)(x + r1 * HIDDEN + col);
            float hn2 = (c[nt][2] - mu1) * rs1 * gg.x + be.x;
            float hn3 = (c[nt][3] - mu1) * rs1 * gg.y + be.y;
            float g2 = 0.5f * hn2 * (1.f + erff(hn2 * inv_sqrt2));
            float g3 = 0.5f * hn3 * (1.f + erff(hn3 * inv_sqrt2));
            *(float2*)(out + r1 * HIDDEN + col) = make_float2(xv.x + g2, xv.y + g3);
        }
    }
}

extern "C" void kernel_launch(void* const* d_in, const int* in_sizes, int n_in,
                              void* d_out, int out_size) {
    const float* x     = (const float*)d_in[0];
    const int*   ei    = (const int*)d_in[1];
    const int*   et    = (const int*)d_in[2];
    const float* Wmsg  = (const float*)d_in[3];
    const float* bmsg  = (const float*)d_in[4];
    const float* Wupd  = (const float*)d_in[5];
    const float* bupd  = (const float*)d_in[6];
    const float* gamma = (const float*)d_in[7];
    const float* beta  = (const float*)d_in[8];
    float* out = (float*)d_out;

    const int PROJ_SM = (128 + 64) * TPAD * 4;   // 101376 B
    const int UPD_SM  = 256 * TPAD * 4;          // 135168 B
    cudaFuncSetAttribute(k_proj,   cudaFuncAttributeMaxDynamicSharedMemorySize, PROJ_SM);
    cudaFuncSetAttribute(k_update, cudaFuncAttributeMaxDynamicSharedMemorySize, UPD_SM);

    k_zero<<<512, 256>>>();

    dim3 gproj((N_NODES + 127) / 128, 12);
    k_proj<<<gproj, 256, PROJ_SM>>>(x, Wmsg);

    k_hist<<<(N_EDGES + 255) / 256, 256>>>(ei, et);

    long long sthreads = (long long)N_EDGES * 32;
    k_scatter<<<(unsigned)((sthreads + 255) / 256), 256>>>(ei, et);

    k_finalize<<<(N_NODES * HIDDEN + 255) / 256, 256>>>(bmsg);

    k_update<<<(N_NODES + 127) / 128, 256, UPD_SM>>>(x, Wupd, bupd, gamma, beta, out);
}

// round 4
// speedup vs baseline: 1.9461x; 1.3185x over previous
#include <cuda_runtime.h>
#include <math.h>
#include <stdint.h>

#define HIDDEN  128
#define N_NODES 50000
#define N_EDGES 600000
#define LN_EPS  1e-5f
#define TPAD    132   // smem row stride (floats): bank=(4*row+k)%32 -> conflict-free frags

// Scratch (static device arrays: no allocation allowed)
__device__ float g_A[N_NODES * 3 * HIDDEN];    // per-node src-side typed projections
__device__ float g_B[N_NODES * 3 * HIDDEN];    // per-node dst-side typed projections
__device__ float g_agg[N_NODES * HIDDEN];      // aggregated messages (gather-written)
__device__ int   g_cnt[N_NODES * 4];           // per-node per-type edge counts
__device__ int   g_pos[N_NODES];               // CSR fill cursors
__device__ int   g_off[N_NODES + 1];           // CSR row offsets
__device__ int   g_csr[N_EDGES];               // packed (src<<2)|type
__device__ float g_Wt[768 * 128];              // Wmsg transposed: [j][k], j=part*384+t*128+h
__device__ float g_Wut[128 * 256];             // Wupd transposed: [h][k]

#define CPA16(sa, gp)      asm volatile("cp.async.cg.shared.global [%0],[%1],16;" :: "r"(sa), "l"(gp))
#define CPA16Z(sa, gp, sz) asm volatile("cp.async.cg.shared.global [%0],[%1],16,%2;" :: "r"(sa), "l"(gp), "r"(sz))
#define CPA_COMMIT()       asm volatile("cp.async.commit_group;")
#define CPA_WAIT(n)        asm volatile("cp.async.wait_group %0;" :: "n"(n))

#define MMA_TF32(c, a, b)                                                        \
    asm volatile(                                                                \
        "mma.sync.aligned.m16n8k8.row.col.f32.tf32.tf32.f32 "                    \
        "{%0,%1,%2,%3},{%4,%5,%6,%7},{%8,%9},{%0,%1,%2,%3};"                     \
        : "+f"((c)[0]), "+f"((c)[1]), "+f"((c)[2]), "+f"((c)[3])                 \
        : "r"((a)[0]), "r"((a)[1]), "r"((a)[2]), "r"((a)[3]),                    \
          "r"((b)[0]), "r"((b)[1]))

// ---------------- zero small scratch (counters only; g_agg fully overwritten) ----------------
__global__ void k_zero() {
    int i = blockIdx.x * blockDim.x + threadIdx.x;
    int stride = gridDim.x * blockDim.x;
    for (int j = i; j < N_NODES * 4; j += stride) g_cnt[j] = 0;
    for (int j = i; j < N_NODES; j += stride) g_pos[j] = 0;
}

// ---------------- transpose Wmsg -> g_Wt [j][k] (k contiguous) ----------------
__global__ void k_wt(const float* __restrict__ Wmsg) {
    __shared__ float ts[32][33];
    int mat = blockIdx.x >> 4;       // 0..5
    int tile = blockIdx.x & 15;
    int ti = tile >> 2, tj = tile & 3;   // k-tile, h-tile
    int t_ = mat % 3, part = mat / 3;
    int rx = threadIdx.x & 31, ry = threadIdx.x >> 5;
#pragma unroll
    for (int p = 0; p < 4; p++) {
        int k = ti * 32 + ry + p * 8;
        ts[ry + p * 8][rx] = Wmsg[(t_ * 256 + part * 128 + k) * 128 + tj * 32 + rx];
    }
    __syncthreads();
#pragma unroll
    for (int p = 0; p < 4; p++) {
        int row = ry + p * 8;
        g_Wt[(part * 384 + t_ * 128 + tj * 32 + row) * 128 + ti * 32 + rx] = ts[rx][row];
    }
}

// ---------------- transpose Wupd -> g_Wut [h][k] ----------------
__global__ void k_wt2(const float* __restrict__ Wupd) {
    __shared__ float ts[32][33];
    int ti = blockIdx.x >> 2, tj = blockIdx.x & 3;   // k-tile (8), h-tile (4)
    int rx = threadIdx.x & 31, ry = threadIdx.x >> 5;
#pragma unroll
    for (int p = 0; p < 4; p++)
        ts[ry + p * 8][rx] = Wupd[(ti * 32 + ry + p * 8) * 128 + tj * 32 + rx];
    __syncthreads();
#pragma unroll
    for (int p = 0; p < 4; p++) {
        int row = ry + p * 8;
        g_Wut[(tj * 32 + row) * 256 + ti * 32 + rx] = ts[rx][row];
    }
}

// ---------------- projection GEMM: x[N,128] @ Wt^T -> g_A, g_B (tf32, cp.async pipelined) -------
// 512 threads, block = 128 rows; x tile loaded once, 12 W-tiles (64 cols) double-buffered.
__global__ void __launch_bounds__(512) k_proj(const float* __restrict__ x) {
    extern __shared__ float sm[];
    float* xs  = sm;                    // [128][TPAD]
    float* wsb = sm + 128 * TPAD;       // 2 x [64][TPAD]
    const int tid = threadIdx.x;
    const int n0 = blockIdx.x * 128;
    const uint32_t xs_b = (uint32_t)__cvta_generic_to_shared(xs);
    const uint32_t ws_b = (uint32_t)__cvta_generic_to_shared(wsb);

    for (int i = tid; i < 4096; i += 512) {       // x tile: 128 x 32 chunks
        int m = i >> 5, k4 = i & 31;
        int n = n0 + m;
        uint32_t sa = xs_b + (m * TPAD + k4 * 4) * 4;
        const float* gp = x + (size_t)n * 128 + k4 * 4;
        int sz = (n < N_NODES) ? 16 : 0;
        CPA16Z(sa, gp, sz);
    }
    CPA_COMMIT();
    for (int i = tid; i < 2048; i += 512) {       // W tile 0
        int r = i >> 5, k4 = i & 31;
        CPA16(ws_b + (r * TPAD + k4 * 4) * 4, g_Wt + r * 128 + k4 * 4);
    }
    CPA_COMMIT();

    const int w = tid >> 5, lane = tid & 31;
    const int gid = lane >> 2, tig = lane & 3;
    const int m0 = (w & 7) * 16;
    const int nw = (w >> 3) * 32;

    for (int jt = 0; jt < 12; jt++) {
        if (jt + 1 < 12) {
            uint32_t dst = ws_b + ((jt + 1) & 1) * 64 * TPAD * 4;
            const float* src = g_Wt + (jt + 1) * 64 * 128;
            for (int i = tid; i < 2048; i += 512) {
                int r = i >> 5, k4 = i & 31;
                CPA16(dst + (r * TPAD + k4 * 4) * 4, src + r * 128 + k4 * 4);
            }
            CPA_COMMIT();
            CPA_WAIT(1);
        } else {
            CPA_WAIT(0);
        }
        __syncthreads();

        const uint32_t* As = (const uint32_t*)xs;
        const uint32_t* Ws = (const uint32_t*)(wsb + (jt & 1) * 64 * TPAD);

        float c[4][4];
#pragma unroll
        for (int nt = 0; nt < 4; nt++)
#pragma unroll
            for (int q = 0; q < 4; q++) c[nt][q] = 0.f;

#pragma unroll
        for (int ks = 0; ks < 16; ks++) {
            int kb = ks * 8;
            uint32_t a[4];
            const uint32_t* ap = As + (m0 + gid) * TPAD + kb + tig;
            a[0] = ap[0];
            a[1] = ap[8 * TPAD];
            a[2] = ap[4];
            a[3] = ap[8 * TPAD + 4];
#pragma unroll
            for (int nt = 0; nt < 4; nt++) {
                uint32_t b[2];
                const uint32_t* bp = Ws + (nw + nt * 8 + gid) * TPAD + kb + tig;
                b[0] = bp[0];
                b[1] = bp[4];
                MMA_TF32(c[nt], a, b);
            }
        }

        int j0 = jt * 64;
        int part = (j0 >= 384) ? 1 : 0;
        float* outp = part ? g_B : g_A;
        int jbase = j0 - part * 384 + nw;
        int r0 = n0 + m0 + gid;
#pragma unroll
        for (int nt = 0; nt < 4; nt++) {
            int col = jbase + nt * 8 + tig * 2;
            if (r0 < N_NODES)
                *(float2*)(outp + (size_t)r0 * 384 + col) = make_float2(c[nt][0], c[nt][1]);
            if (r0 + 8 < N_NODES)
                *(float2*)(outp + (size_t)(r0 + 8) * 384 + col) = make_float2(c[nt][2], c[nt][3]);
        }
        __syncthreads();
    }
}

// ---------------- per-(dst,type) histogram ----------------
__global__ void k_hist(const int* __restrict__ ei, const int* __restrict__ et) {
    int e = blockIdx.x * blockDim.x + threadIdx.x;
    if (e >= N_EDGES) return;
    atomicAdd(&g_cnt[ei[N_EDGES + e] * 4 + et[e]], 1);
}

// ---------------- exclusive prefix scan of degrees (single block) ----------------
__global__ void k_scan() {
    __shared__ int wsum[32];
    __shared__ int carry;
    const int tid = threadIdx.x, lane = tid & 31, wid = tid >> 5;
    if (tid == 0) carry = 0;
    __syncthreads();
    for (int base = 0; base < N_NODES; base += 1024) {
        int n = base + tid;
        int v = 0;
        if (n < N_NODES) v = g_cnt[n * 4] + g_cnt[n * 4 + 1] + g_cnt[n * 4 + 2];
        int xv = v;
#pragma unroll
        for (int o = 1; o < 32; o <<= 1) {
            int y = __shfl_up_sync(0xffffffffu, xv, o);
            if (lane >= o) xv += y;
        }
        if (lane == 31) wsum[wid] = xv;
        __syncthreads();
        if (wid == 0) {
            int s = wsum[lane];
#pragma unroll
            for (int o = 1; o < 32; o <<= 1) {
                int y = __shfl_up_sync(0xffffffffu, s, o);
                if (lane >= o) s += y;
            }
            wsum[lane] = s;
        }
        __syncthreads();
        int excl = xv - v + (wid > 0 ? wsum[wid - 1] : 0) + carry;
        if (n < N_NODES) g_off[n] = excl;
        __syncthreads();
        if (tid == 0) carry += wsum[31];
        __syncthreads();
    }
    if (threadIdx.x == 0) g_off[N_NODES] = carry;
}

// ---------------- CSR bucket fill ----------------
__global__ void k_fill(const int* __restrict__ ei, const int* __restrict__ et) {
    int e = blockIdx.x * blockDim.x + threadIdx.x;
    if (e >= N_EDGES) return;
    int dst = ei[N_EDGES + e];
    int p = atomicAdd(&g_pos[dst], 1);
    g_csr[g_off[dst] + p] = (ei[e] << 2) | et[e];
}

// ---------------- gather-aggregate + fused finalize (one warp per dst node) ----------------
__global__ void k_agg(const float* __restrict__ bmsg) {
    int n = (blockIdx.x * blockDim.x + threadIdx.x) >> 5;
    if (n >= N_NODES) return;
    int lane = threadIdx.x & 31;
    int beg = g_off[n], end = g_off[n + 1];
    float4 acc = make_float4(0.f, 0.f, 0.f, 0.f);
    for (int i = beg; i < end; i++) {
        int p = g_csr[i];
        int src = p >> 2, t = p & 3;
        float4 v = ((const float4*)g_A)[(src * 3 + t) * 32 + lane];
        acc.x += v.x; acc.y += v.y; acc.z += v.z; acc.w += v.w;
    }
    float f0 = (float)g_cnt[n * 4 + 0];
    float f1 = (float)g_cnt[n * 4 + 1];
    float f2 = (float)g_cnt[n * 4 + 2];
    float4 b0 = ((const float4*)g_B)[(n * 3 + 0) * 32 + lane];
    float4 b1 = ((const float4*)g_B)[(n * 3 + 1) * 32 + lane];
    float4 b2 = ((const float4*)g_B)[(n * 3 + 2) * 32 + lane];
    float4 m0 = ((const float4*)bmsg)[lane];
    float4 m1 = ((const float4*)bmsg)[32 + lane];
    float4 m2 = ((const float4*)bmsg)[64 + lane];
    acc.x += f0 * (b0.x + m0.x) + f1 * (b1.x + m1.x) + f2 * (b2.x + m2.x);
    acc.y += f0 * (b0.y + m0.y) + f1 * (b1.y + m1.y) + f2 * (b2.y + m2.y);
    acc.z += f0 * (b0.z + m0.z) + f1 * (b1.z + m1.z) + f2 * (b2.z + m2.z);
    acc.w += f0 * (b0.w + m0.w) + f1 * (b1.w + m1.w) + f2 * (b2.w + m2.w);
    float inv = 1.f / fmaxf(f0 + f1 + f2, 1.f);
    acc.x *= inv; acc.y *= inv; acc.z *= inv; acc.w *= inv;
    ((float4*)g_agg)[n * 32 + lane] = acc;
}

// ---------------- update GEMM (tf32, cp.async) + fused LN/GELU/residual ----------------
__global__ void __launch_bounds__(256) k_update(const float* __restrict__ x,
                                                const float* __restrict__ bupd,
                                                const float* __restrict__ gamma,
                                                const float* __restrict__ beta,
                                                float* __restrict__ out) {
    extern __shared__ float sm[];
    float* Is = sm;                 // [128][TPAD]
    float* Ws = sm + 128 * TPAD;    // [128][TPAD]
    const int tid = threadIdx.x;
    const int n0 = blockIdx.x * 128;
    const uint32_t is_b = (uint32_t)__cvta_generic_to_shared(Is);
    const uint32_t ws_b = (uint32_t)__cvta_generic_to_shared(Ws);
    const int w = tid >> 5, lane = tid & 31;
    const int gid = lane >> 2, tig = lane & 3;
    const int m0 = w * 16;

    float c[16][4];
#pragma unroll
    for (int nt = 0; nt < 16; nt++)
#pragma unroll
        for (int q = 0; q < 4; q++) c[nt][q] = 0.f;

    for (int kt = 0; kt < 2; kt++) {
        const float* src = kt ? g_agg : x;
        for (int i = tid; i < 4096; i += 256) {
            int m = i >> 5, k4 = i & 31;
            int n = n0 + m;
            int sz = (n < N_NODES) ? 16 : 0;
            CPA16Z(is_b + (m * TPAD + k4 * 4) * 4, src + (size_t)n * 128 + k4 * 4, sz);
        }
        for (int i = tid; i < 4096; i += 256) {
            int h = i >> 5, k4 = i & 31;
            CPA16(ws_b + (h * TPAD + k4 * 4) * 4, g_Wut + h * 256 + kt * 128 + k4 * 4);
        }
        CPA_COMMIT();
        CPA_WAIT(0);
        __syncthreads();

        const uint32_t* IsU = (const uint32_t*)Is;
        const uint32_t* WsU = (const uint32_t*)Ws;
#pragma unroll
        for (int ks = 0; ks < 16; ks++) {
            int kb = ks * 8;
            uint32_t a[4];
            const uint32_t* ap = IsU + (m0 + gid) * TPAD + kb + tig;
            a[0] = ap[0];
            a[1] = ap[8 * TPAD];
            a[2] = ap[4];
            a[3] = ap[8 * TPAD + 4];
#pragma unroll
            for (int nt = 0; nt < 16; nt++) {
                uint32_t b[2];
                const uint32_t* bp = WsU + (nt * 8 + gid) * TPAD + kb + tig;
                b[0] = bp[0];
                b[1] = bp[4];
                MMA_TF32(c[nt], a, b);
            }
        }
        __syncthreads();
    }

    // Epilogue: bias + LayerNorm (lane-quad shfl) + GELU + residual
    const int r0 = n0 + m0 + gid;
    const int r1 = r0 + 8;
    float s0 = 0.f, q0 = 0.f, s1 = 0.f, q1 = 0.f;
#pragma unroll
    for (int nt = 0; nt < 16; nt++) {
        int col = nt * 8 + tig * 2;
        float2 bb = *(const float2*)(bupd + col);
        float h0 = c[nt][0] + bb.x, h1 = c[nt][1] + bb.y;
        float h2 = c[nt][2] + bb.x, h3 = c[nt][3] + bb.y;
        c[nt][0] = h0; c[nt][1] = h1; c[nt][2] = h2; c[nt][3] = h3;
        s0 += h0 + h1; q0 += h0 * h0 + h1 * h1;
        s1 += h2 + h3; q1 += h2 * h2 + h3 * h3;
    }
#pragma unroll
    for (int o = 1; o <= 2; o <<= 1) {
        s0 += __shfl_xor_sync(0xffffffffu, s0, o);
        q0 += __shfl_xor_sync(0xffffffffu, q0, o);
        s1 += __shfl_xor_sync(0xffffffffu, s1, o);
        q1 += __shfl_xor_sync(0xffffffffu, q1, o);
    }
    const float inv_h = 1.f / 128.f;
    float mu0 = s0 * inv_h, var0 = q0 * inv_h - mu0 * mu0;
    float mu1 = s1 * inv_h, var1 = q1 * inv_h - mu1 * mu1;
    float rs0 = rsqrtf(var0 + LN_EPS);
    float rs1 = rsqrtf(var1 + LN_EPS);
    const float inv_sqrt2 = 0.70710678118654752f;

#pragma unroll
    for (int nt = 0; nt < 16; nt++) {
        int col = nt * 8 + tig * 2;
        float2 gg = *(const float2*)(gamma + col);
        float2 be = *(const float2*)(beta + col);
        if (r0 < N_NODES) {
            float2 xv = *(const float2*)(x + (size_t)r0 * HIDDEN + col);
            float hn0 = (c[nt][0] - mu0) * rs0 * gg.x + be.x;
            float hn1 = (c[nt][1] - mu0) * rs0 * gg.y + be.y;
            float g0 = 0.5f * hn0 * (1.f + erff(hn0 * inv_sqrt2));
            float g1 = 0.5f * hn1 * (1.f + erff(hn1 * inv_sqrt2));
            *(float2*)(out + (size_t)r0 * HIDDEN + col) = make_float2(xv.x + g0, xv.y + g1);
        }
        if (r1 < N_NODES) {
            float2 xv = *(const float2*)(x + (size_t)r1 * HIDDEN + col);
            float hn2 = (c[nt][2] - mu1) * rs1 * gg.x + be.x;
            float hn3 = (c[nt][3] - mu1) * rs1 * gg.y + be.y;
            float g2 = 0.5f * hn2 * (1.f + erff(hn2 * inv_sqrt2));
            float g3 = 0.5f * hn3 * (1.f + erff(hn3 * inv_sqrt2));
            *(float2*)(out + (size_t)r1 * HIDDEN + col) = make_float2(xv.x + g2, xv.y + g3);
        }
    }
}

extern "C" void kernel_launch(void* const* d_in, const int* in_sizes, int n_in,
                              void* d_out, int out_size) {
    const float* x     = (const float*)d_in[0];
    const int*   ei    = (const int*)d_in[1];
    const int*   et    = (const int*)d_in[2];
    const float* Wmsg  = (const float*)d_in[3];
    const float* bmsg  = (const float*)d_in[4];
    const float* Wupd  = (const float*)d_in[5];
    const float* bupd  = (const float*)d_in[6];
    const float* gamma = (const float*)d_in[7];
    const float* beta  = (const float*)d_in[8];
    float* out = (float*)d_out;

    const int PROJ_SM = (128 + 2 * 64) * TPAD * 4;   // 135168 B
    const int UPD_SM  = 256 * TPAD * 4;              // 135168 B
    cudaFuncSetAttribute(k_proj,   cudaFuncAttributeMaxDynamicSharedMemorySize, PROJ_SM);
    cudaFuncSetAttribute(k_update, cudaFuncAttributeMaxDynamicSharedMemorySize, UPD_SM);

    k_zero<<<128, 256>>>();
    k_wt<<<96, 256>>>(Wmsg);
    k_wt2<<<32, 256>>>(Wupd);

    k_proj<<<(N_NODES + 127) / 128, 512, PROJ_SM>>>(x);

    k_hist<<<(N_EDGES + 255) / 256, 256>>>(ei, et);
    k_scan<<<1, 1024>>>();
    k_fill<<<(N_EDGES + 255) / 256, 256>>>(ei, et);
    k_agg<<<(N_NODES + 7) / 8, 256>>>(bmsg);

    k_update<<<(N_NODES + 127) / 128, 256, UPD_SM>>>(x, bupd, gamma, beta, out);
}

// round 7
// speedup vs baseline: 2.2750x; 1.1690x over previous
#include <cuda_runtime.h>
#include <math.h>
#include <stdint.h>

#define HIDDEN  128
#define N_NODES 50000
#define N_EDGES 600000
#define LN_EPS  1e-5f
#define APAD    132   // A-tile smem stride: bank=(4g+t)%32 conflict-free scalar frag loads
#define BPAD    136   // B-tile smem stride: (8g+2t)%32 conflict-free LDS.64 frag loads

// Scratch (static device arrays: no allocation allowed)
__device__ float g_A[N_NODES * 3 * HIDDEN];    // per-node src-side typed projections
__device__ float g_agg[N_NODES * HIDDEN];      // B-term partial (proj epi) -> full agg
__device__ int   g_cnt[N_NODES * 4];           // per-node per-type edge counts
__device__ int   g_pos[N_NODES];               // CSR fill cursors
__device__ int   g_off[N_NODES + 1];           // CSR row offsets
__device__ int   g_csr[N_EDGES];               // packed (src<<2)|type
__device__ float g_Wt[768 * 128];              // Wmsg^T [j][k], k perm-within-8
__device__ float g_Wut[128 * 256];             // Wupd^T [h][k], k perm-within-8

__device__ __constant__ int JT[12] = {0,1,2,3,4,5, 6,8,10, 7,9,11};

#define CPA16(sa, gp)      asm volatile("cp.async.cg.shared.global [%0],[%1],16;" :: "r"(sa), "l"(gp))
#define CPA16Z(sa, gp, sz) asm volatile("cp.async.cg.shared.global [%0],[%1],16,%2;" :: "r"(sa), "l"(gp), "r"(sz))
#define CPA_COMMIT()       asm volatile("cp.async.commit_group;")
#define CPA_WAIT(n)        asm volatile("cp.async.wait_group %0;" :: "n"(n))

#define MMA_TF32(c, a, b)                                                        \
    asm volatile(                                                                \
        "mma.sync.aligned.m16n8k8.row.col.f32.tf32.tf32.f32 "                    \
        "{%0,%1,%2,%3},{%4,%5,%6,%7},{%8,%9},{%0,%1,%2,%3};"                     \
        : "+f"((c)[0]), "+f"((c)[1]), "+f"((c)[2]), "+f"((c)[3])                 \
        : "r"((a)[0]), "r"((a)[1]), "r"((a)[2]), "r"((a)[3]),                    \
          "r"((b)[0]), "r"((b)[1]))

__device__ __forceinline__ int perm8(int k) {   // (k,k+4) pairs adjacent within 8-group
    return (k & ~7) | (((k & 3) << 1) | ((k >> 2) & 1));
}

// ---------------- zero counters ----------------
__global__ void k_zero() {
    int i = blockIdx.x * blockDim.x + threadIdx.x;
    int stride = gridDim.x * blockDim.x;
    for (int j = i; j < N_NODES * 4; j += stride) g_cnt[j] = 0;
    for (int j = i; j < N_NODES; j += stride) g_pos[j] = 0;
}

// ---------------- transpose Wmsg -> g_Wt [j][perm(k)] ----------------
__global__ void k_wt(const float* __restrict__ Wmsg) {
    __shared__ float ts[32][33];
    int mat = blockIdx.x >> 4;
    int tile = blockIdx.x & 15;
    int ti = tile >> 2, tj = tile & 3;
    int t_ = mat % 3, part = mat / 3;
    int rx = threadIdx.x & 31, ry = threadIdx.x >> 5;
#pragma unroll
    for (int p = 0; p < 4; p++) {
        int k = ti * 32 + ry + p * 8;
        ts[ry + p * 8][rx] = Wmsg[(t_ * 256 + part * 128 + k) * 128 + tj * 32 + rx];
    }
    __syncthreads();
#pragma unroll
    for (int p = 0; p < 4; p++) {
        int row = ry + p * 8;
        int kp = perm8(ti * 32 + rx);
        g_Wt[(part * 384 + t_ * 128 + tj * 32 + row) * 128 + kp] = ts[rx][row];
    }
}

// ---------------- transpose Wupd -> g_Wut [h][perm(k)] ----------------
__global__ void k_wt2(const float* __restrict__ Wupd) {
    __shared__ float ts[32][33];
    int ti = blockIdx.x >> 2, tj = blockIdx.x & 3;
    int rx = threadIdx.x & 31, ry = threadIdx.x >> 5;
#pragma unroll
    for (int p = 0; p < 4; p++)
        ts[ry + p * 8][rx] = Wupd[(ti * 32 + ry + p * 8) * 128 + tj * 32 + rx];
    __syncthreads();
#pragma unroll
    for (int p = 0; p < 4; p++) {
        int row = ry + p * 8;
        int kp = perm8(ti * 32 + rx);
        g_Wut[(tj * 32 + row) * 256 + kp] = ts[rx][row];
    }
}

// ---------------- per-(dst,type) histogram (runs BEFORE k_proj) ----------------
__global__ void k_hist(const int* __restrict__ ei, const int* __restrict__ et) {
    int e = blockIdx.x * blockDim.x + threadIdx.x;
    if (e >= N_EDGES) return;
    atomicAdd(&g_cnt[ei[N_EDGES + e] * 4 + et[e]], 1);
}

// ---------------- projection GEMM: A-in-regs, permuted W, B-term folded into g_agg ----------
__global__ void __launch_bounds__(512) k_proj(const float* __restrict__ x,
                                              const float* __restrict__ bmsg) {
    extern __shared__ float sm[];
    float* xs  = sm;                    // [128][APAD]
    float* wsb = sm + 128 * APAD;       // 2 x [64][BPAD]
    const int tid = threadIdx.x;
    const int n0 = blockIdx.x * 128;
    const uint32_t xs_b = (uint32_t)__cvta_generic_to_shared(xs);
    const uint32_t ws_b = (uint32_t)__cvta_generic_to_shared(wsb);

    for (int i = tid; i < 4096; i += 512) {       // x tile: 128 rows x 32 16B-chunks
        int m = i >> 5, k4 = i & 31;
        int n = n0 + m;
        int sz = (n < N_NODES) ? 16 : 0;
        CPA16Z(xs_b + (m * APAD + k4 * 4) * 4, x + (size_t)n * 128 + k4 * 4, sz);
    }
    CPA_COMMIT();
    for (int i = tid; i < 2048; i += 512) {       // W tile 0 (JT[0]=0)
        int r = i >> 5, k4 = i & 31;
        CPA16(ws_b + (r * BPAD + k4 * 4) * 4, g_Wt + r * 128 + k4 * 4);
    }
    CPA_COMMIT();

    const int w = tid >> 5, lane = tid & 31;
    const int gid = lane >> 2, tig = lane & 3;
    const int m0 = (w & 7) * 16;
    const int nw = (w >> 3) * 32;
    const int r0 = n0 + m0 + gid;

    // Wait x tile (group age 1 = W0 still pending), load A fragments into registers once.
    CPA_WAIT(1);
    __syncthreads();
    uint32_t a[16][4];
    {
        const uint32_t* As = (const uint32_t*)xs;
#pragma unroll
        for (int ks = 0; ks < 16; ks++) {
            const uint32_t* ap = As + (m0 + gid) * APAD + ks * 8 + tig;
            a[ks][0] = ap[0];
            a[ks][1] = ap[8 * APAD];
            a[ks][2] = ap[4];
            a[ks][3] = ap[8 * APAD + 4];
        }
    }

    float accB[4][4];

    for (int idx = 0; idx < 12; idx++) {
        if (idx + 1 < 12) {
            uint32_t dst = ws_b + ((idx + 1) & 1) * 64 * BPAD * 4;
            const float* src = g_Wt + JT[idx + 1] * 64 * 128;
            for (int i = tid; i < 2048; i += 512) {
                int r = i >> 5, k4 = i & 31;
                CPA16(dst + (r * BPAD + k4 * 4) * 4, src + r * 128 + k4 * 4);
            }
            CPA_COMMIT();
            CPA_WAIT(1);
        } else {
            CPA_WAIT(0);
        }
        __syncthreads();

        const uint32_t* Ws = (const uint32_t*)(wsb + (idx & 1) * 64 * BPAD);

        float c[4][4];
#pragma unroll
        for (int nt = 0; nt < 4; nt++)
#pragma unroll
            for (int q = 0; q < 4; q++) c[nt][q] = 0.f;

#pragma unroll
        for (int ks = 0; ks < 16; ks++) {
#pragma unroll
            for (int nt = 0; nt < 4; nt++) {
                uint2 bv = *(const uint2*)(Ws + (nw + nt * 8 + gid) * BPAD + ks * 8 + tig * 2);
                uint32_t b[2] = {bv.x, bv.y};
                MMA_TF32(c[nt], a[ks], b);
            }
        }

        int j0 = JT[idx] * 64;
        if (j0 < 384) {
            // A-part: store per-(node,type) src projections
            int jbase = j0 + nw;
#pragma unroll
            for (int nt = 0; nt < 4; nt++) {
                int col = jbase + nt * 8 + tig * 2;
                if (r0 < N_NODES)
                    *(float2*)(g_A + (size_t)r0 * 384 + col) = make_float2(c[nt][0], c[nt][1]);
                if (r0 + 8 < N_NODES)
                    *(float2*)(g_A + (size_t)(r0 + 8) * 384 + col) = make_float2(c[nt][2], c[nt][3]);
            }
        } else {
            // B-part: accumulate cnt-weighted (B + bmsg) across t = 0,1,2 (JT ordering)
            int jj = j0 - 384;
            int t = jj >> 7;
            int h0 = jj & 127;   // 0 or 64
            float f0 = (r0 < N_NODES)     ? (float)g_cnt[r0 * 4 + t]       : 0.f;
            float f1 = (r0 + 8 < N_NODES) ? (float)g_cnt[(r0 + 8) * 4 + t] : 0.f;
#pragma unroll
            for (int nt = 0; nt < 4; nt++) {
                int hcol = h0 + nw + nt * 8 + tig * 2;
                float2 bm = *(const float2*)(bmsg + t * 128 + hcol);
                if (t == 0) { accB[nt][0] = 0.f; accB[nt][1] = 0.f; accB[nt][2] = 0.f; accB[nt][3] = 0.f; }
                accB[nt][0] += f0 * (c[nt][0] + bm.x);
                accB[nt][1] += f0 * (c[nt][1] + bm.y);
                accB[nt][2] += f1 * (c[nt][2] + bm.x);
                accB[nt][3] += f1 * (c[nt][3] + bm.y);
                if (t == 2) {
                    if (r0 < N_NODES)
                        *(float2*)(g_agg + (size_t)r0 * 128 + hcol) = make_float2(accB[nt][0], accB[nt][1]);
                    if (r0 + 8 < N_NODES)
                        *(float2*)(g_agg + (size_t)(r0 + 8) * 128 + hcol) = make_float2(accB[nt][2], accB[nt][3]);
                }
            }
        }
        __syncthreads();
    }
}

// ---------------- exclusive prefix scan of degrees (single block) ----------------
__global__ void k_scan() {
    __shared__ int wsum[32];
    __shared__ int carry;
    const int tid = threadIdx.x, lane = tid & 31, wid = tid >> 5;
    if (tid == 0) carry = 0;
    __syncthreads();
    for (int base = 0; base < N_NODES; base += 1024) {
        int n = base + tid;
        int v = 0;
        if (n < N_NODES) v = g_cnt[n * 4] + g_cnt[n * 4 + 1] + g_cnt[n * 4 + 2];
        int xv = v;
#pragma unroll
        for (int o = 1; o < 32; o <<= 1) {
            int y = __shfl_up_sync(0xffffffffu, xv, o);
            if (lane >= o) xv += y;
        }
        if (lane == 31) wsum[wid] = xv;
        __syncthreads();
        if (wid == 0) {
            int s = wsum[lane];
#pragma unroll
            for (int o = 1; o < 32; o <<= 1) {
                int y = __shfl_up_sync(0xffffffffu, s, o);
                if (lane >= o) s += y;
            }
            wsum[lane] = s;
        }
        __syncthreads();
        int excl = xv - v + (wid > 0 ? wsum[wid - 1] : 0) + carry;
        if (n < N_NODES) g_off[n] = excl;
        __syncthreads();
        if (tid == 0) carry += wsum[31];
        __syncthreads();
    }
    if (threadIdx.x == 0) g_off[N_NODES] = carry;
}

// ---------------- CSR bucket fill ----------------
__global__ void k_fill(const int* __restrict__ ei, const int* __restrict__ et) {
    int e = blockIdx.x * blockDim.x + threadIdx.x;
    if (e >= N_EDGES) return;
    int dst = ei[N_EDGES + e];
    int p = atomicAdd(&g_pos[dst], 1);
    g_csr[g_off[dst] + p] = (ei[e] << 2) | et[e];
}

// ---------------- gather-aggregate (one warp per dst); B-term already in g_agg ----------------
__global__ void k_agg() {
    int n = (blockIdx.x * blockDim.x + threadIdx.x) >> 5;
    if (n >= N_NODES) return;
    int lane = threadIdx.x & 31;
    int beg = g_off[n], end = g_off[n + 1];
    float4 acc = ((const float4*)g_agg)[n * 32 + lane];   // cnt-weighted B + bias partial
    for (int i = beg; i < end; i++) {
        int p = __ldg(&g_csr[i]);
        int src = p >> 2, t = p & 3;
        float4 v = __ldg(&((const float4*)g_A)[(src * 3 + t) * 32 + lane]);
        acc.x += v.x; acc.y += v.y; acc.z += v.z; acc.w += v.w;
    }
    float inv = 1.f / fmaxf((float)(end - beg), 1.f);
    acc.x *= inv; acc.y *= inv; acc.z *= inv; acc.w *= inv;
    ((float4*)g_agg)[n * 32 + lane] = acc;
}

// ---------------- update GEMM (tf32, permuted W, cp.async) + fused LN/GELU/residual -----------
__global__ void __launch_bounds__(256) k_update(const float* __restrict__ x,
                                                const float* __restrict__ bupd,
                                                const float* __restrict__ gamma,
                                                const float* __restrict__ beta,
                                                float* __restrict__ out) {
    extern __shared__ float sm[];
    float* Is = sm;                 // [128][APAD]
    float* Ws = sm + 128 * APAD;    // [128][BPAD]
    const int tid = threadIdx.x;
    const int n0 = blockIdx.x * 128;
    const uint32_t is_b = (uint32_t)__cvta_generic_to_shared(Is);
    const uint32_t ws_b = (uint32_t)__cvta_generic_to_shared(Ws);
    const int w = tid >> 5, lane = tid & 31;
    const int gid = lane >> 2, tig = lane & 3;
    const int m0 = w * 16;

    float c[16][4];
#pragma unroll
    for (int nt = 0; nt < 16; nt++)
#pragma unroll
        for (int q = 0; q < 4; q++) c[nt][q] = 0.f;

    for (int kt = 0; kt < 2; kt++) {
        const float* src = kt ? g_agg : x;
        for (int i = tid; i < 4096; i += 256) {
            int m = i >> 5, k4 = i & 31;
            int n = n0 + m;
            int sz = (n < N_NODES) ? 16 : 0;
            CPA16Z(is_b + (m * APAD + k4 * 4) * 4, src + (size_t)n * 128 + k4 * 4, sz);
        }
        for (int i = tid; i < 4096; i += 256) {
            int h = i >> 5, k4 = i & 31;
            CPA16(ws_b + (h * BPAD + k4 * 4) * 4, g_Wut + h * 256 + kt * 128 + k4 * 4);
        }
        CPA_COMMIT();
        CPA_WAIT(0);
        __syncthreads();

        const uint32_t* IsU = (const uint32_t*)Is;
        const uint32_t* WsU = (const uint32_t*)Ws;
#pragma unroll
        for (int ks = 0; ks < 16; ks++) {
            int kb = ks * 8;
            uint32_t a[4];
            const uint32_t* ap = IsU + (m0 + gid) * APAD + kb + tig;
            a[0] = ap[0];
            a[1] = ap[8 * APAD];
            a[2] = ap[4];
            a[3] = ap[8 * APAD + 4];
#pragma unroll
            for (int nt = 0; nt < 16; nt++) {
                uint2 bv = *(const uint2*)(WsU + (nt * 8 + gid) * BPAD + kb + tig * 2);
                uint32_t b[2] = {bv.x, bv.y};
                MMA_TF32(c[nt], a, b);
            }
        }
        __syncthreads();
    }

    // Epilogue: bias + LayerNorm (lane-quad shfl) + GELU + residual
    const int r0 = n0 + m0 + gid;
    const int r1 = r0 + 8;
    float s0 = 0.f, q0 = 0.f, s1 = 0.f, q1 = 0.f;
#pragma unroll
    for (int nt = 0; nt < 16; nt++) {
        int col = nt * 8 + tig * 2;
        float2 bb = *(const float2*)(bupd + col);
        float h0 = c[nt][0] + bb.x, h1 = c[nt][1] + bb.y;
        float h2 = c[nt][2] + bb.x, h3 = c[nt][3] + bb.y;
        c[nt][0] = h0; c[nt][1] = h1; c[nt][2] = h2; c[nt][3] = h3;
        s0 += h0 + h1; q0 += h0 * h0 + h1 * h1;
        s1 += h2 + h3; q1 += h2 * h2 + h3 * h3;
    }
#pragma unroll
    for (int o = 1; o <= 2; o <<= 1) {
        s0 += __shfl_xor_sync(0xffffffffu, s0, o);
        q0 += __shfl_xor_sync(0xffffffffu, q0, o);
        s1 += __shfl_xor_sync(0xffffffffu, s1, o);
        q1 += __shfl_xor_sync(0xffffffffu, q1, o);
    }
    const float inv_h = 1.f / 128.f;
    float mu0 = s0 * inv_h, var0 = q0 * inv_h - mu0 * mu0;
    float mu1 = s1 * inv_h, var1 = q1 * inv_h - mu1 * mu1;
    float rs0 = rsqrtf(var0 + LN_EPS);
    float rs1 = rsqrtf(var1 + LN_EPS);
    const float inv_sqrt2 = 0.70710678118654752f;

#pragma unroll
    for (int nt = 0; nt < 16; nt++) {
        int col = nt * 8 + tig * 2;
        float2 gg = *(const float2*)(gamma + col);
        float2 be = *(const float2*)(beta + col);
        if (r0 < N_NODES) {
            float2 xv = *(const float2*)(x + (size_t)r0 * HIDDEN + col);
            float hn0 = (c[nt][0] - mu0) * rs0 * gg.x + be.x;
            float hn1 = (c[nt][1] - mu0) * rs0 * gg.y + be.y;
            float g0 = 0.5f * hn0 * (1.f + erff(hn0 * inv_sqrt2));
            float g1 = 0.5f * hn1 * (1.f + erff(hn1 * inv_sqrt2));
            *(float2*)(out + (size_t)r0 * HIDDEN + col) = make_float2(xv.x + g0, xv.y + g1);
        }
        if (r1 < N_NODES) {
            float2 xv = *(const float2*)(x + (size_t)r1 * HIDDEN + col);
            float hn2 = (c[nt][2] - mu1) * rs1 * gg.x + be.x;
            float hn3 = (c[nt][3] - mu1) * rs1 * gg.y + be.y;
            float g2 = 0.5f * hn2 * (1.f + erff(hn2 * inv_sqrt2));
            float g3 = 0.5f * hn3 * (1.f + erff(hn3 * inv_sqrt2));
            *(float2*)(out + (size_t)r1 * HIDDEN + col) = make_float2(xv.x + g2, xv.y + g3);
        }
    }
}

extern "C" void kernel_launch(void* const* d_in, const int* in_sizes, int n_in,
                              void* d_out, int out_size) {
    const float* x     = (const float*)d_in[0];
    const int*   ei    = (const int*)d_in[1];
    const int*   et    = (const int*)d_in[2];
    const float* Wmsg  = (const float*)d_in[3];
    const float* bmsg  = (const float*)d_in[4];
    const float* Wupd  = (const float*)d_in[5];
    const float* bupd  = (const float*)d_in[6];
    const float* gamma = (const float*)d_in[7];
    const float* beta  = (const float*)d_in[8];
    float* out = (float*)d_out;

    const int PROJ_SM = (128 * APAD + 2 * 64 * BPAD) * 4;   // 137216 B
    const int UPD_SM  = (128 * APAD + 128 * BPAD) * 4;      // 137216 B
    cudaFuncSetAttribute(k_proj,   cudaFuncAttributeMaxDynamicSharedMemorySize, PROJ_SM);
    cudaFuncSetAttribute(k_update, cudaFuncAttributeMaxDynamicSharedMemorySize, UPD_SM);

    k_zero<<<128, 256>>>();
    k_wt<<<96, 256>>>(Wmsg);
    k_wt2<<<32, 256>>>(Wupd);
    k_hist<<<(N_EDGES + 255) / 256, 256>>>(ei, et);   // cnt needed by k_proj epilogue

    k_proj<<<(N_NODES + 127) / 128, 512, PROJ_SM>>>(x, bmsg);

    k_scan<<<1, 1024>>>();
    k_fill<<<(N_EDGES + 255) / 256, 256>>>(ei, et);
    k_agg<<<(N_NODES + 7) / 8, 256>>>();

    k_update<<<(N_NODES + 127) / 128, 256, UPD_SM>>>(x, bupd, gamma, beta, out);
}

// round 8
// speedup vs baseline: 2.5025x; 1.1000x over previous
#include <cuda_runtime.h>
#include <math.h>
#include <stdint.h>

#define HIDDEN  128
#define N_NODES 50000
#define N_EDGES 600000
#define LN_EPS  1e-5f
#define APAD    132   // A-tile smem stride: conflict-free scalar frag loads
#define BPAD    136   // B-tile smem stride: conflict-free LDS.64 frag loads

// Scratch (static device arrays: no allocation allowed)
__device__ uint32_t g_Ah[N_NODES * 3 * 64];    // per-node typed projections, bf16x2 packed
__device__ float g_agg[N_NODES * HIDDEN];      // B-term partial (proj epi) -> full agg
__device__ int   g_cnt[N_NODES * 4];           // per-node per-type edge counts
__device__ int   g_pos[N_NODES];               // CSR fill cursors
__device__ int   g_off[N_NODES + 1];           // CSR row offsets
__device__ int   g_csr[N_EDGES];               // packed (src<<2)|type
__device__ float g_Wt[768 * 128];              // Wmsg^T [j][k], k perm-within-8
__device__ float g_Wut[128 * 256];             // Wupd^T [h][k], k perm-within-8

__device__ __constant__ int JT[12] = {0,1,2,3,4,5, 6,8,10, 7,9,11};

#define CPA16(sa, gp)      asm volatile("cp.async.cg.shared.global [%0],[%1],16;" :: "r"(sa), "l"(gp))
#define CPA16Z(sa, gp, sz) asm volatile("cp.async.cg.shared.global [%0],[%1],16,%2;" :: "r"(sa), "l"(gp), "r"(sz))
#define CPA_COMMIT()       asm volatile("cp.async.commit_group;")
#define CPA_WAIT(n)        asm volatile("cp.async.wait_group %0;" :: "n"(n))

#define MMA_TF32(c, a, b)                                                        \
    asm volatile(                                                                \
        "mma.sync.aligned.m16n8k8.row.col.f32.tf32.tf32.f32 "                    \
        "{%0,%1,%2,%3},{%4,%5,%6,%7},{%8,%9},{%0,%1,%2,%3};"                     \
        : "+f"((c)[0]), "+f"((c)[1]), "+f"((c)[2]), "+f"((c)[3])                 \
        : "r"((a)[0]), "r"((a)[1]), "r"((a)[2]), "r"((a)[3]),                    \
          "r"((b)[0]), "r"((b)[1]))

__device__ __forceinline__ int perm8(int k) {   // (k,k+4) pairs adjacent within 8-group
    return (k & ~7) | (((k & 3) << 1) | ((k >> 2) & 1));
}

__device__ __forceinline__ uint32_t pack_bf16(float lo, float hi) {
    uint32_t r;
    asm("cvt.rn.bf16x2.f32 %0, %1, %2;" : "=r"(r) : "f"(hi), "f"(lo));
    return r;
}

// ---------------- fused prep: zero counters | transpose Wmsg | transpose Wupd | histogram -----
__global__ void k_prep(const float* __restrict__ Wmsg, const float* __restrict__ Wupd,
                       const int* __restrict__ ei, const int* __restrict__ et) {
    __shared__ float ts[32][33];
    const int b = blockIdx.x;
    const int tid = threadIdx.x;
    if (b < 128) {
        // zero counters
        int i = b * 256 + tid;
        int stride = 128 * 256;
        for (int j = i; j < N_NODES * 4; j += stride) g_cnt[j] = 0;
        for (int j = i; j < N_NODES; j += stride) g_pos[j] = 0;
    } else if (b < 224) {
        // transpose Wmsg -> g_Wt [j][perm(k)]
        int bb = b - 128;
        int mat = bb >> 4;
        int tile = bb & 15;
        int ti = tile >> 2, tj = tile & 3;
        int t_ = mat % 3, part = mat / 3;
        int rx = tid & 31, ry = tid >> 5;
#pragma unroll
        for (int p = 0; p < 4; p++) {
            int k = ti * 32 + ry + p * 8;
            ts[ry + p * 8][rx] = Wmsg[(t_ * 256 + part * 128 + k) * 128 + tj * 32 + rx];
        }
        __syncthreads();
#pragma unroll
        for (int p = 0; p < 4; p++) {
            int row = ry + p * 8;
            int kp = perm8(ti * 32 + rx);
            g_Wt[(part * 384 + t_ * 128 + tj * 32 + row) * 128 + kp] = ts[rx][row];
        }
    } else if (b < 256) {
        // transpose Wupd -> g_Wut [h][perm(k)]
        int bb = b - 224;
        int ti = bb >> 2, tj = bb & 3;
        int rx = tid & 31, ry = tid >> 5;
#pragma unroll
        for (int p = 0; p < 4; p++)
            ts[ry + p * 8][rx] = Wupd[(ti * 32 + ry + p * 8) * 128 + tj * 32 + rx];
        __syncthreads();
#pragma unroll
        for (int p = 0; p < 4; p++) {
            int row = ry + p * 8;
            int kp = perm8(ti * 32 + rx);
            g_Wut[(tj * 32 + row) * 256 + kp] = ts[rx][row];
        }
    } else {
        // histogram (needs zeroed g_cnt: hist blocks only touch counters after the
        // grid-wide implicit dependency? NO — must not race with zeroing blocks!)
        // Safe because zeroing and histogram touch the same g_cnt: we guard with a
        // grid-phase trick: histogram blocks spin... -> instead: zero is done by the
        // FIRST 128 blocks which, at grid launch, are scheduled before block 256+?
        // Not guaranteed. So histogram here works on a separate accumulator pass:
        // we instead count via atomicAdd AFTER zero, enforced by having zeroing
        // done in THIS same block range split. To stay safe, histogram is keyed to
        // g_cnt zeroed at END of previous graph replay... not deterministic either.
        // => handled by doing zero+hist in the same blocks below (never reached).
    }
}

// ---------------- per-(dst,type) histogram (separate: needs zero complete) ----------------
__global__ void k_hist(const int* __restrict__ ei, const int* __restrict__ et) {
    int e = blockIdx.x * blockDim.x + threadIdx.x;
    if (e >= N_EDGES) return;
    atomicAdd(&g_cnt[ei[N_EDGES + e] * 4 + et[e]], 1);
}

// ---------------- projection GEMM: A-in-regs, permuted W, bf16 A-out, B-term into g_agg ------
__global__ void __launch_bounds__(512) k_proj(const float* __restrict__ x,
                                              const float* __restrict__ bmsg) {
    extern __shared__ float sm[];
    float* xs  = sm;                    // [128][APAD]
    float* wsb = sm + 128 * APAD;       // 2 x [64][BPAD]
    const int tid = threadIdx.x;
    const int n0 = blockIdx.x * 128;
    const uint32_t xs_b = (uint32_t)__cvta_generic_to_shared(xs);
    const uint32_t ws_b = (uint32_t)__cvta_generic_to_shared(wsb);

    for (int i = tid; i < 4096; i += 512) {       // x tile: 128 rows x 32 16B-chunks
        int m = i >> 5, k4 = i & 31;
        int n = n0 + m;
        int sz = (n < N_NODES) ? 16 : 0;
        CPA16Z(xs_b + (m * APAD + k4 * 4) * 4, x + (size_t)n * 128 + k4 * 4, sz);
    }
    CPA_COMMIT();
    for (int i = tid; i < 2048; i += 512) {       // W tile 0 (JT[0]=0)
        int r = i >> 5, k4 = i & 31;
        CPA16(ws_b + (r * BPAD + k4 * 4) * 4, g_Wt + r * 128 + k4 * 4);
    }
    CPA_COMMIT();

    const int w = tid >> 5, lane = tid & 31;
    const int gid = lane >> 2, tig = lane & 3;
    const int m0 = (w & 7) * 16;
    const int nw = (w >> 3) * 32;
    const int r0 = n0 + m0 + gid;

    CPA_WAIT(1);
    __syncthreads();
    uint32_t a[16][4];
    {
        const uint32_t* As = (const uint32_t*)xs;
#pragma unroll
        for (int ks = 0; ks < 16; ks++) {
            const uint32_t* ap = As + (m0 + gid) * APAD + ks * 8 + tig;
            a[ks][0] = ap[0];
            a[ks][1] = ap[8 * APAD];
            a[ks][2] = ap[4];
            a[ks][3] = ap[8 * APAD + 4];
        }
    }

    float accB[4][4];

    for (int idx = 0; idx < 12; idx++) {
        if (idx + 1 < 12) {
            uint32_t dst = ws_b + ((idx + 1) & 1) * 64 * BPAD * 4;
            const float* src = g_Wt + JT[idx + 1] * 64 * 128;
            for (int i = tid; i < 2048; i += 512) {
                int r = i >> 5, k4 = i & 31;
                CPA16(dst + (r * BPAD + k4 * 4) * 4, src + r * 128 + k4 * 4);
            }
            CPA_COMMIT();
            CPA_WAIT(1);
        } else {
            CPA_WAIT(0);
        }
        __syncthreads();

        const uint32_t* Ws = (const uint32_t*)(wsb + (idx & 1) * 64 * BPAD);

        float c[4][4];
#pragma unroll
        for (int nt = 0; nt < 4; nt++)
#pragma unroll
            for (int q = 0; q < 4; q++) c[nt][q] = 0.f;

#pragma unroll
        for (int ks = 0; ks < 16; ks++) {
#pragma unroll
            for (int nt = 0; nt < 4; nt++) {
                uint2 bv = *(const uint2*)(Ws + (nw + nt * 8 + gid) * BPAD + ks * 8 + tig * 2);
                uint32_t b[2] = {bv.x, bv.y};
                MMA_TF32(c[nt], a[ks], b);
            }
        }

        int j0 = JT[idx] * 64;
        if (j0 < 384) {
            // A-part: store bf16x2-packed projections; channel pair (col, col+1) at uint idx col/2
#pragma unroll
            for (int nt = 0; nt < 4; nt++) {
                int col = j0 + nw + nt * 8 + tig * 2;   // within [0,384)
                uint32_t p01 = pack_bf16(c[nt][0], c[nt][1]);
                uint32_t p23 = pack_bf16(c[nt][2], c[nt][3]);
                if (r0 < N_NODES)
                    g_Ah[(size_t)r0 * 192 + (col >> 1)] = p01;
                if (r0 + 8 < N_NODES)
                    g_Ah[(size_t)(r0 + 8) * 192 + (col >> 1)] = p23;
            }
        } else {
            // B-part: accumulate cnt-weighted (B + bmsg) across t = 0,1,2 (JT ordering)
            int jj = j0 - 384;
            int t = jj >> 7;
            int h0 = jj & 127;   // 0 or 64
            float f0 = (r0 < N_NODES)     ? (float)g_cnt[r0 * 4 + t]       : 0.f;
            float f1 = (r0 + 8 < N_NODES) ? (float)g_cnt[(r0 + 8) * 4 + t] : 0.f;
#pragma unroll
            for (int nt = 0; nt < 4; nt++) {
                int hcol = h0 + nw + nt * 8 + tig * 2;
                float2 bm = *(const float2*)(bmsg + t * 128 + hcol);
                if (t == 0) { accB[nt][0] = 0.f; accB[nt][1] = 0.f; accB[nt][2] = 0.f; accB[nt][3] = 0.f; }
                accB[nt][0] += f0 * (c[nt][0] + bm.x);
                accB[nt][1] += f0 * (c[nt][1] + bm.y);
                accB[nt][2] += f1 * (c[nt][2] + bm.x);
                accB[nt][3] += f1 * (c[nt][3] + bm.y);
                if (t == 2) {
                    if (r0 < N_NODES)
                        *(float2*)(g_agg + (size_t)r0 * 128 + hcol) = make_float2(accB[nt][0], accB[nt][1]);
                    if (r0 + 8 < N_NODES)
                        *(float2*)(g_agg + (size_t)(r0 + 8) * 128 + hcol) = make_float2(accB[nt][2], accB[nt][3]);
                }
            }
        }
        __syncthreads();
    }
}

// ---------------- exclusive prefix scan of degrees (single block) ----------------
__global__ void k_scan() {
    __shared__ int wsum[32];
    __shared__ int carry;
    const int tid = threadIdx.x, lane = tid & 31, wid = tid >> 5;
    if (tid == 0) carry = 0;
    __syncthreads();
    for (int base = 0; base < N_NODES; base += 1024) {
        int n = base + tid;
        int v = 0;
        if (n < N_NODES) v = g_cnt[n * 4] + g_cnt[n * 4 + 1] + g_cnt[n * 4 + 2];
        int xv = v;
#pragma unroll
        for (int o = 1; o < 32; o <<= 1) {
            int y = __shfl_up_sync(0xffffffffu, xv, o);
            if (lane >= o) xv += y;
        }
        if (lane == 31) wsum[wid] = xv;
        __syncthreads();
        if (wid == 0) {
            int s = wsum[lane];
#pragma unroll
            for (int o = 1; o < 32; o <<= 1) {
                int y = __shfl_up_sync(0xffffffffu, s, o);
                if (lane >= o) s += y;
            }
            wsum[lane] = s;
        }
        __syncthreads();
        int excl = xv - v + (wid > 0 ? wsum[wid - 1] : 0) + carry;
        if (n < N_NODES) g_off[n] = excl;
        __syncthreads();
        if (tid == 0) carry += wsum[31];
        __syncthreads();
    }
    if (threadIdx.x == 0) g_off[N_NODES] = carry;
}

// ---------------- CSR bucket fill ----------------
__global__ void k_fill(const int* __restrict__ ei, const int* __restrict__ et) {
    int e = blockIdx.x * blockDim.x + threadIdx.x;
    if (e >= N_EDGES) return;
    int dst = ei[N_EDGES + e];
    int p = atomicAdd(&g_pos[dst], 1);
    g_csr[g_off[dst] + p] = (ei[e] << 2) | et[e];
}

// ---------------- gather-aggregate (one warp per dst); bf16 messages, dual-acc unroll --------
__global__ void k_agg() {
    int n = (blockIdx.x * blockDim.x + threadIdx.x) >> 5;
    if (n >= N_NODES) return;
    int lane = threadIdx.x & 31;
    int beg = g_off[n], end = g_off[n + 1];
    float4 acc = ((const float4*)g_agg)[n * 32 + lane];   // cnt-weighted B + bias partial
    float4 acc2 = make_float4(0.f, 0.f, 0.f, 0.f);
    int i = beg;
    for (; i + 2 <= end; i += 2) {
        int p0 = __ldg(&g_csr[i]);
        int p1 = __ldg(&g_csr[i + 1]);
        uint2 v0 = __ldg((const uint2*)g_Ah + (size_t)((p0 >> 2) * 3 + (p0 & 3)) * 32 + lane);
        uint2 v1 = __ldg((const uint2*)g_Ah + (size_t)((p1 >> 2) * 3 + (p1 & 3)) * 32 + lane);
        acc.x  += __uint_as_float(v0.x << 16);
        acc.y  += __uint_as_float(v0.x & 0xffff0000u);
        acc.z  += __uint_as_float(v0.y << 16);
        acc.w  += __uint_as_float(v0.y & 0xffff0000u);
        acc2.x += __uint_as_float(v1.x << 16);
        acc2.y += __uint_as_float(v1.x & 0xffff0000u);
        acc2.z += __uint_as_float(v1.y << 16);
        acc2.w += __uint_as_float(v1.y & 0xffff0000u);
    }
    if (i < end) {
        int p0 = __ldg(&g_csr[i]);
        uint2 v0 = __ldg((const uint2*)g_Ah + (size_t)((p0 >> 2) * 3 + (p0 & 3)) * 32 + lane);
        acc.x += __uint_as_float(v0.x << 16);
        acc.y += __uint_as_float(v0.x & 0xffff0000u);
        acc.z += __uint_as_float(v0.y << 16);
        acc.w += __uint_as_float(v0.y & 0xffff0000u);
    }
    acc.x += acc2.x; acc.y += acc2.y; acc.z += acc2.z; acc.w += acc2.w;
    float inv = 1.f / fmaxf((float)(end - beg), 1.f);
    acc.x *= inv; acc.y *= inv; acc.z *= inv; acc.w *= inv;
    ((float4*)g_agg)[n * 32 + lane] = acc;
}

// ---------------- update GEMM (tf32, permuted W, cp.async) + fused LN/GELU/residual -----------
__global__ void __launch_bounds__(256) k_update(const float* __restrict__ x,
                                                const float* __restrict__ bupd,
                                                const float* __restrict__ gamma,
                                                const float* __restrict__ beta,
                                                float* __restrict__ out) {
    extern __shared__ float sm[];
    float* Is = sm;                 // [128][APAD]
    float* Ws = sm + 128 * APAD;    // [128][BPAD]
    const int tid = threadIdx.x;
    const int n0 = blockIdx.x * 128;
    const uint32_t is_b = (uint32_t)__cvta_generic_to_shared(Is);
    const uint32_t ws_b = (uint32_t)__cvta_generic_to_shared(Ws);
    const int w = tid >> 5, lane = tid & 31;
    const int gid = lane >> 2, tig = lane & 3;
    const int m0 = w * 16;

    float c[16][4];
#pragma unroll
    for (int nt = 0; nt < 16; nt++)
#pragma unroll
        for (int q = 0; q < 4; q++) c[nt][q] = 0.f;

    for (int kt = 0; kt < 2; kt++) {
        const float* src = kt ? g_agg : x;
        for (int i = tid; i < 4096; i += 256) {
            int m = i >> 5, k4 = i & 31;
            int n = n0 + m;
            int sz = (n < N_NODES) ? 16 : 0;
            CPA16Z(is_b + (m * APAD + k4 * 4) * 4, src + (size_t)n * 128 + k4 * 4, sz);
        }
        for (int i = tid; i < 4096; i += 256) {
            int h = i >> 5, k4 = i & 31;
            CPA16(ws_b + (h * BPAD + k4 * 4) * 4, g_Wut + h * 256 + kt * 128 + k4 * 4);
        }
        CPA_COMMIT();
        CPA_WAIT(0);
        __syncthreads();

        const uint32_t* IsU = (const uint32_t*)Is;
        const uint32_t* WsU = (const uint32_t*)Ws;
#pragma unroll
        for (int ks = 0; ks < 16; ks++) {
            int kb = ks * 8;
            uint32_t a[4];
            const uint32_t* ap = IsU + (m0 + gid) * APAD + kb + tig;
            a[0] = ap[0];
            a[1] = ap[8 * APAD];
            a[2] = ap[4];
            a[3] = ap[8 * APAD + 4];
#pragma unroll
            for (int nt = 0; nt < 16; nt++) {
                uint2 bv = *(const uint2*)(WsU + (nt * 8 + gid) * BPAD + kb + tig * 2);
                uint32_t b[2] = {bv.x, bv.y};
                MMA_TF32(c[nt], a, b);
            }
        }
        __syncthreads();
    }

    // Epilogue: bias + LayerNorm (lane-quad shfl) + GELU + residual
    const int r0 = n0 + m0 + gid;
    const int r1 = r0 + 8;
    float s0 = 0.f, q0 = 0.f, s1 = 0.f, q1 = 0.f;
#pragma unroll
    for (int nt = 0; nt < 16; nt++) {
        int col = nt * 8 + tig * 2;
        float2 bb = *(const float2*)(bupd + col);
        float h0 = c[nt][0] + bb.x, h1 = c[nt][1] + bb.y;
        float h2 = c[nt][2] + bb.x, h3 = c[nt][3] + bb.y;
        c[nt][0] = h0; c[nt][1] = h1; c[nt][2] = h2; c[nt][3] = h3;
        s0 += h0 + h1; q0 += h0 * h0 + h1 * h1;
        s1 += h2 + h3; q1 += h2 * h2 + h3 * h3;
    }
#pragma unroll
    for (int o = 1; o <= 2; o <<= 1) {
        s0 += __shfl_xor_sync(0xffffffffu, s0, o);
        q0 += __shfl_xor_sync(0xffffffffu, q0, o);
        s1 += __shfl_xor_sync(0xffffffffu, s1, o);
        q1 += __shfl_xor_sync(0xffffffffu, q1, o);
    }
    const float inv_h = 1.f / 128.f;
    float mu0 = s0 * inv_h, var0 = q0 * inv_h - mu0 * mu0;
    float mu1 = s1 * inv_h, var1 = q1 * inv_h - mu1 * mu1;
    float rs0 = rsqrtf(var0 + LN_EPS);
    float rs1 = rsqrtf(var1 + LN_EPS);
    const float inv_sqrt2 = 0.70710678118654752f;

#pragma unroll
    for (int nt = 0; nt < 16; nt++) {
        int col = nt * 8 + tig * 2;
        float2 gg = *(const float2*)(gamma + col);
        float2 be = *(const float2*)(beta + col);
        if (r0 < N_NODES) {
            float2 xv = *(const float2*)(x + (size_t)r0 * HIDDEN + col);
            float hn0 = (c[nt][0] - mu0) * rs0 * gg.x + be.x;
            float hn1 = (c[nt][1] - mu0) * rs0 * gg.y + be.y;
            float g0 = 0.5f * hn0 * (1.f + erff(hn0 * inv_sqrt2));
            float g1 = 0.5f * hn1 * (1.f + erff(hn1 * inv_sqrt2));
            *(float2*)(out + (size_t)r0 * HIDDEN + col) = make_float2(xv.x + g0, xv.y + g1);
        }
        if (r1 < N_NODES) {
            float2 xv = *(const float2*)(x + (size_t)r1 * HIDDEN + col);
            float hn2 = (c[nt][2] - mu1) * rs1 * gg.x + be.x;
            float hn3 = (c[nt][3] - mu1) * rs1 * gg.y + be.y;
            float g2 = 0.5f * hn2 * (1.f + erff(hn2 * inv_sqrt2));
            float g3 = 0.5f * hn3 * (1.f + erff(hn3 * inv_sqrt2));
            *(float2*)(out + (size_t)r1 * HIDDEN + col) = make_float2(xv.x + g2, xv.y + g3);
        }
    }
}

extern "C" void kernel_launch(void* const* d_in, const int* in_sizes, int n_in,
                              void* d_out, int out_size) {
    const float* x     = (const float*)d_in[0];
    const int*   ei    = (const int*)d_in[1];
    const int*   et    = (const int*)d_in[2];
    const float* Wmsg  = (const float*)d_in[3];
    const float* bmsg  = (const float*)d_in[4];
    const float* Wupd  = (const float*)d_in[5];
    const float* bupd  = (const float*)d_in[6];
    const float* gamma = (const float*)d_in[7];
    const float* beta  = (const float*)d_in[8];
    float* out = (float*)d_out;

    const int PROJ_SM = (128 * APAD + 2 * 64 * BPAD) * 4;   // 137216 B
    const int UPD_SM  = (128 * APAD + 128 * BPAD) * 4;      // 137216 B
    cudaFuncSetAttribute(k_proj,   cudaFuncAttributeMaxDynamicSharedMemorySize, PROJ_SM);
    cudaFuncSetAttribute(k_update, cudaFuncAttributeMaxDynamicSharedMemorySize, UPD_SM);

    k_prep<<<256, 256>>>(Wmsg, Wupd, ei, et);               // zero + both W transposes
    k_hist<<<(N_EDGES + 255) / 256, 256>>>(ei, et);         // after zero (separate launch)

    k_proj<<<(N_NODES + 127) / 128, 512, PROJ_SM>>>(x, bmsg);

    k_scan<<<1, 1024>>>();
    k_fill<<<(N_EDGES + 255) / 256, 256>>>(ei, et);
    k_agg<<<(N_NODES + 7) / 8, 256>>>();

    k_update<<<(N_NODES + 127) / 128, 256, UPD_SM>>>(x, bupd, gamma, beta, out);
}

// round 10
// speedup vs baseline: 2.9547x; 1.1807x over previous
#include <cuda_runtime.h>
#include <math.h>
#include <stdint.h>

#define HIDDEN  128
#define N_NODES 50000
#define N_EDGES 600000
#define LN_EPS  1e-5f
#define APAD    132   // A-tile smem stride: conflict-free scalar frag loads
#define BPAD    136   // B-tile smem stride: conflict-free LDS.64 frag loads
#define SCAN_BLOCKS ((N_NODES + 1023) / 1024)   // 49

// Scratch (static device arrays: no allocation allowed)
__device__ uint32_t g_Ah[N_NODES * 3 * 64];    // per-node typed projections, bf16x2 packed
__device__ float g_agg[N_NODES * HIDDEN];      // B-term partial (proj epi) -> full agg
__device__ int   g_cnt[N_NODES * 4];           // per-node per-type edge counts
__device__ int   g_pos[N_NODES];               // CSR fill cursors
__device__ int   g_off[N_NODES + 1];           // CSR row offsets
__device__ int   g_csr[N_EDGES];               // packed (src<<2)|type
__device__ int   g_bsum[SCAN_BLOCKS];          // per-scan-block totals -> exclusive prefixes
__device__ float g_Wt[768 * 128];              // Wmsg^T [j][k], k perm-within-8
__device__ float g_Wut[128 * 256];             // Wupd^T [h][k], k perm-within-8

__device__ __constant__ int JT[12] = {0,1,2,3,4,5, 6,8,10, 7,9,11};

#define CPA16(sa, gp)      asm volatile("cp.async.cg.shared.global [%0],[%1],16;" :: "r"(sa), "l"(gp))
#define CPA16Z(sa, gp, sz) asm volatile("cp.async.cg.shared.global [%0],[%1],16,%2;" :: "r"(sa), "l"(gp), "r"(sz))
#define CPA_COMMIT()       asm volatile("cp.async.commit_group;")
#define CPA_WAIT(n)        asm volatile("cp.async.wait_group %0;" :: "n"(n))

#define MMA_TF32(c, a, b)                                                        \
    asm volatile(                                                                \
        "mma.sync.aligned.m16n8k8.row.col.f32.tf32.tf32.f32 "                    \
        "{%0,%1,%2,%3},{%4,%5,%6,%7},{%8,%9},{%0,%1,%2,%3};"                     \
        : "+f"((c)[0]), "+f"((c)[1]), "+f"((c)[2]), "+f"((c)[3])                 \
        : "r"((a)[0]), "r"((a)[1]), "r"((a)[2]), "r"((a)[3]),                    \
          "r"((b)[0]), "r"((b)[1]))

__device__ __forceinline__ int perm8(int k) {   // (k,k+4) pairs adjacent within 8-group
    return (k & ~7) | (((k & 3) << 1) | ((k >> 2) & 1));
}

__device__ __forceinline__ uint32_t pack_bf16(float lo, float hi) {
    uint32_t r;
    asm("cvt.rn.bf16x2.f32 %0, %1, %2;" : "=r"(r) : "f"(hi), "f"(lo));
    return r;
}

// ---------------- fused prep: zero counters | transpose Wmsg | transpose Wupd ----------------
__global__ void k_prep(const float* __restrict__ Wmsg, const float* __restrict__ Wupd) {
    __shared__ float ts[32][33];
    const int b = blockIdx.x;
    const int tid = threadIdx.x;
    if (b < 128) {
        int i = b * 256 + tid;
        int stride = 128 * 256;
        for (int j = i; j < N_NODES * 4; j += stride) g_cnt[j] = 0;
        for (int j = i; j < N_NODES; j += stride) g_pos[j] = 0;
    } else if (b < 224) {
        int bb = b - 128;
        int mat = bb >> 4;
        int tile = bb & 15;
        int ti = tile >> 2, tj = tile & 3;
        int t_ = mat % 3, part = mat / 3;
        int rx = tid & 31, ry = tid >> 5;
#pragma unroll
        for (int p = 0; p < 4; p++) {
            int k = ti * 32 + ry + p * 8;
            ts[ry + p * 8][rx] = Wmsg[(t_ * 256 + part * 128 + k) * 128 + tj * 32 + rx];
        }
        __syncthreads();
#pragma unroll
        for (int p = 0; p < 4; p++) {
            int row = ry + p * 8;
            int kp = perm8(ti * 32 + rx);
            g_Wt[(part * 384 + t_ * 128 + tj * 32 + row) * 128 + kp] = ts[rx][row];
        }
    } else {
        int bb = b - 224;
        int ti = bb >> 2, tj = bb & 3;
        int rx = tid & 31, ry = tid >> 5;
#pragma unroll
        for (int p = 0; p < 4; p++)
            ts[ry + p * 8][rx] = Wupd[(ti * 32 + ry + p * 8) * 128 + tj * 32 + rx];
        __syncthreads();
#pragma unroll
        for (int p = 0; p < 4; p++) {
            int row = ry + p * 8;
            int kp = perm8(ti * 32 + rx);
            g_Wut[(tj * 32 + row) * 256 + kp] = ts[rx][row];
        }
    }
}

// ---------------- per-(dst,type) histogram ----------------
__global__ void k_hist(const int* __restrict__ ei, const int* __restrict__ et) {
    int e = blockIdx.x * blockDim.x + threadIdx.x;
    if (e >= N_EDGES) return;
    atomicAdd(&g_cnt[ei[N_EDGES + e] * 4 + et[e]], 1);
}

// ---------------- projection GEMM: A-in-regs, permuted W, bf16 A-out, B-term into g_agg ------
__global__ void __launch_bounds__(512) k_proj(const float* __restrict__ x,
                                              const float* __restrict__ bmsg) {
    extern __shared__ float sm[];
    float* xs  = sm;                    // [128][APAD]
    float* wsb = sm + 128 * APAD;       // 2 x [64][BPAD]
    const int tid = threadIdx.x;
    const int n0 = blockIdx.x * 128;
    const uint32_t xs_b = (uint32_t)__cvta_generic_to_shared(xs);
    const uint32_t ws_b = (uint32_t)__cvta_generic_to_shared(wsb);

    for (int i = tid; i < 4096; i += 512) {
        int m = i >> 5, k4 = i & 31;
        int n = n0 + m;
        int sz = (n < N_NODES) ? 16 : 0;
        CPA16Z(xs_b + (m * APAD + k4 * 4) * 4, x + (size_t)n * 128 + k4 * 4, sz);
    }
    CPA_COMMIT();
    for (int i = tid; i < 2048; i += 512) {
        int r = i >> 5, k4 = i & 31;
        CPA16(ws_b + (r * BPAD + k4 * 4) * 4, g_Wt + r * 128 + k4 * 4);
    }
    CPA_COMMIT();

    const int w = tid >> 5, lane = tid & 31;
    const int gid = lane >> 2, tig = lane & 3;
    const int m0 = (w & 7) * 16;
    const int nw = (w >> 3) * 32;
    const int r0 = n0 + m0 + gid;

    CPA_WAIT(1);
    __syncthreads();
    uint32_t a[16][4];
    {
        const uint32_t* As = (const uint32_t*)xs;
#pragma unroll
        for (int ks = 0; ks < 16; ks++) {
            const uint32_t* ap = As + (m0 + gid) * APAD + ks * 8 + tig;
            a[ks][0] = ap[0];
            a[ks][1] = ap[8 * APAD];
            a[ks][2] = ap[4];
            a[ks][3] = ap[8 * APAD + 4];
        }
    }

    float accB[4][4];

    for (int idx = 0; idx < 12; idx++) {
        if (idx + 1 < 12) {
            uint32_t dst = ws_b + ((idx + 1) & 1) * 64 * BPAD * 4;
            const float* src = g_Wt + JT[idx + 1] * 64 * 128;
            for (int i = tid; i < 2048; i += 512) {
                int r = i >> 5, k4 = i & 31;
                CPA16(dst + (r * BPAD + k4 * 4) * 4, src + r * 128 + k4 * 4);
            }
            CPA_COMMIT();
            CPA_WAIT(1);
        } else {
            CPA_WAIT(0);
        }
        __syncthreads();

        const uint32_t* Ws = (const uint32_t*)(wsb + (idx & 1) * 64 * BPAD);

        float c[4][4];
#pragma unroll
        for (int nt = 0; nt < 4; nt++)
#pragma unroll
            for (int q = 0; q < 4; q++) c[nt][q] = 0.f;

#pragma unroll
        for (int ks = 0; ks < 16; ks++) {
#pragma unroll
            for (int nt = 0; nt < 4; nt++) {
                uint2 bv = *(const uint2*)(Ws + (nw + nt * 8 + gid) * BPAD + ks * 8 + tig * 2);
                uint32_t b[2] = {bv.x, bv.y};
                MMA_TF32(c[nt], a[ks], b);
            }
        }

        int j0 = JT[idx] * 64;
        if (j0 < 384) {
#pragma unroll
            for (int nt = 0; nt < 4; nt++) {
                int col = j0 + nw + nt * 8 + tig * 2;
                uint32_t p01 = pack_bf16(c[nt][0], c[nt][1]);
                uint32_t p23 = pack_bf16(c[nt][2], c[nt][3]);
                if (r0 < N_NODES)
                    g_Ah[(size_t)r0 * 192 + (col >> 1)] = p01;
                if (r0 + 8 < N_NODES)
                    g_Ah[(size_t)(r0 + 8) * 192 + (col >> 1)] = p23;
            }
        } else {
            int jj = j0 - 384;
            int t = jj >> 7;
            int h0 = jj & 127;
            float f0 = (r0 < N_NODES)     ? (float)g_cnt[r0 * 4 + t]       : 0.f;
            float f1 = (r0 + 8 < N_NODES) ? (float)g_cnt[(r0 + 8) * 4 + t] : 0.f;
#pragma unroll
            for (int nt = 0; nt < 4; nt++) {
                int hcol = h0 + nw + nt * 8 + tig * 2;
                float2 bm = *(const float2*)(bmsg + t * 128 + hcol);
                if (t == 0) { accB[nt][0] = 0.f; accB[nt][1] = 0.f; accB[nt][2] = 0.f; accB[nt][3] = 0.f; }
                accB[nt][0] += f0 * (c[nt][0] + bm.x);
                accB[nt][1] += f0 * (c[nt][1] + bm.y);
                accB[nt][2] += f1 * (c[nt][2] + bm.x);
                accB[nt][3] += f1 * (c[nt][3] + bm.y);
                if (t == 2) {
                    if (r0 < N_NODES)
                        *(float2*)(g_agg + (size_t)r0 * 128 + hcol) = make_float2(accB[nt][0], accB[nt][1]);
                    if (r0 + 8 < N_NODES)
                        *(float2*)(g_agg + (size_t)(r0 + 8) * 128 + hcol) = make_float2(accB[nt][2], accB[nt][3]);
                }
            }
        }
        __syncthreads();
    }
}

// ---------------- 3-phase parallel exclusive scan of degrees ----------------
__global__ void k_scan1() {
    __shared__ int wsum[32];
    const int tid = threadIdx.x, lane = tid & 31, wid = tid >> 5;
    int n = blockIdx.x * 1024 + tid;
    int v = 0;
    if (n < N_NODES) v = g_cnt[n * 4] + g_cnt[n * 4 + 1] + g_cnt[n * 4 + 2];
    int xv = v;
#pragma unroll
    for (int o = 1; o < 32; o <<= 1) {
        int y = __shfl_up_sync(0xffffffffu, xv, o);
        if (lane >= o) xv += y;
    }
    if (lane == 31) wsum[wid] = xv;
    __syncthreads();
    if (wid == 0) {
        int s = wsum[lane];
#pragma unroll
        for (int o = 1; o < 32; o <<= 1) {
            int y = __shfl_up_sync(0xffffffffu, s, o);
            if (lane >= o) s += y;
        }
        wsum[lane] = s;
    }
    __syncthreads();
    int excl = xv - v + (wid > 0 ? wsum[wid - 1] : 0);
    if (n < N_NODES) g_off[n] = excl;
    if (tid == 1023) g_bsum[blockIdx.x] = excl + v;
}

__global__ void k_scan2() {
    // single thread: exclusive scan of SCAN_BLOCKS totals (tiny)
    int run = 0;
    for (int b = 0; b < SCAN_BLOCKS; b++) {
        int t = g_bsum[b];
        g_bsum[b] = run;
        run += t;
    }
    g_off[N_NODES] = run;   // == N_EDGES
}

__global__ void k_scan3() {
    int n = blockIdx.x * blockDim.x + threadIdx.x;
    if (n < N_NODES) g_off[n] += g_bsum[n >> 10];
}

// ---------------- CSR bucket fill ----------------
__global__ void k_fill(const int* __restrict__ ei, const int* __restrict__ et) {
    int e = blockIdx.x * blockDim.x + threadIdx.x;
    if (e >= N_EDGES) return;
    int dst = ei[N_EDGES + e];
    int p = atomicAdd(&g_pos[dst], 1);
    g_csr[g_off[dst] + p] = (ei[e] << 2) | et[e];
}

// ---------------- gather-aggregate (one warp per dst); bf16 messages, dual-acc unroll --------
__global__ void k_agg() {
    int n = (blockIdx.x * blockDim.x + threadIdx.x) >> 5;
    if (n >= N_NODES) return;
    int lane = threadIdx.x & 31;
    int beg = g_off[n], end = g_off[n + 1];
    float4 acc = ((const float4*)g_agg)[n * 32 + lane];
    float4 acc2 = make_float4(0.f, 0.f, 0.f, 0.f);
    int i = beg;
    for (; i + 2 <= end; i += 2) {
        int p0 = __ldg(&g_csr[i]);
        int p1 = __ldg(&g_csr[i + 1]);
        uint2 v0 = __ldg((const uint2*)g_Ah + (size_t)((p0 >> 2) * 3 + (p0 & 3)) * 32 + lane);
        uint2 v1 = __ldg((const uint2*)g_Ah + (size_t)((p1 >> 2) * 3 + (p1 & 3)) * 32 + lane);
        acc.x  += __uint_as_float(v0.x << 16);
        acc.y  += __uint_as_float(v0.x & 0xffff0000u);
        acc.z  += __uint_as_float(v0.y << 16);
        acc.w  += __uint_as_float(v0.y & 0xffff0000u);
        acc2.x += __uint_as_float(v1.x << 16);
        acc2.y += __uint_as_float(v1.x & 0xffff0000u);
        acc2.z += __uint_as_float(v1.y << 16);
        acc2.w += __uint_as_float(v1.y & 0xffff0000u);
    }
    if (i < end) {
        int p0 = __ldg(&g_csr[i]);
        uint2 v0 = __ldg((const uint2*)g_Ah + (size_t)((p0 >> 2) * 3 + (p0 & 3)) * 32 + lane);
        acc.x += __uint_as_float(v0.x << 16);
        acc.y += __uint_as_float(v0.x & 0xffff0000u);
        acc.z += __uint_as_float(v0.y << 16);
        acc.w += __uint_as_float(v0.y & 0xffff0000u);
    }
    acc.x += acc2.x; acc.y += acc2.y; acc.z += acc2.z; acc.w += acc2.w;
    float inv = 1.f / fmaxf((float)(end - beg), 1.f);
    acc.x *= inv; acc.y *= inv; acc.z *= inv; acc.w *= inv;
    ((float4*)g_agg)[n * 32 + lane] = acc;
}

// ---------------- update GEMM (tf32, permuted W, cp.async) + fused LN/GELU/residual -----------
__global__ void __launch_bounds__(256) k_update(const float* __restrict__ x,
                                                const float* __restrict__ bupd,
                                                const float* __restrict__ gamma,
                                                const float* __restrict__ beta,
                                                float* __restrict__ out) {
    extern __shared__ float sm[];
    float* Is = sm;                 // [128][APAD]
    float* Ws = sm + 128 * APAD;    // [128][BPAD]
    const int tid = threadIdx.x;
    const int n0 = blockIdx.x * 128;
    const uint32_t is_b = (uint32_t)__cvta_generic_to_shared(Is);
    const uint32_t ws_b = (uint32_t)__cvta_generic_to_shared(Ws);
    const int w = tid >> 5, lane = tid & 31;
    const int gid = lane >> 2, tig = lane & 3;
    const int m0 = w * 16;

    float c[16][4];
#pragma unroll
    for (int nt = 0; nt < 16; nt++)
#pragma unroll
        for (int q = 0; q < 4; q++) c[nt][q] = 0.f;

    for (int kt = 0; kt < 2; kt++) {
        const float* src = kt ? g_agg : x;
        for (int i = tid; i < 4096; i += 256) {
            int m = i >> 5, k4 = i & 31;
            int n = n0 + m;
            int sz = (n < N_NODES) ? 16 : 0;
            CPA16Z(is_b + (m * APAD + k4 * 4) * 4, src + (size_t)n * 128 + k4 * 4, sz);
        }
        for (int i = tid; i < 4096; i += 256) {
            int h = i >> 5, k4 = i & 31;
            CPA16(ws_b + (h * BPAD + k4 * 4) * 4, g_Wut + h * 256 + kt * 128 + k4 * 4);
        }
        CPA_COMMIT();
        CPA_WAIT(0);
        __syncthreads();

        const uint32_t* IsU = (const uint32_t*)Is;
        const uint32_t* WsU = (const uint32_t*)Ws;
#pragma unroll
        for (int ks = 0; ks < 16; ks++) {
            int kb = ks * 8;
            uint32_t a[4];
            const uint32_t* ap = IsU + (m0 + gid) * APAD + kb + tig;
            a[0] = ap[0];
            a[1] = ap[8 * APAD];
            a[2] = ap[4];
            a[3] = ap[8 * APAD + 4];
#pragma unroll
            for (int nt = 0; nt < 16; nt++) {
                uint2 bv = *(const uint2*)(WsU + (nt * 8 + gid) * BPAD + kb + tig * 2);
                uint32_t b[2] = {bv.x, bv.y};
                MMA_TF32(c[nt], a, b);
            }
        }
        __syncthreads();
    }

    const int r0 = n0 + m0 + gid;
    const int r1 = r0 + 8;
    float s0 = 0.f, q0 = 0.f, s1 = 0.f, q1 = 0.f;
#pragma unroll
    for (int nt = 0; nt < 16; nt++) {
        int col = nt * 8 + tig * 2;
        float2 bb = *(const float2*)(bupd + col);
        float h0 = c[nt][0] + bb.x, h1 = c[nt][1] + bb.y;
        float h2 = c[nt][2] + bb.x, h3 = c[nt][3] + bb.y;
        c[nt][0] = h0; c[nt][1] = h1; c[nt][2] = h2; c[nt][3] = h3;
        s0 += h0 + h1; q0 += h0 * h0 + h1 * h1;
        s1 += h2 + h3; q1 += h2 * h2 + h3 * h3;
    }
#pragma unroll
    for (int o = 1; o <= 2; o <<= 1) {
        s0 += __shfl_xor_sync(0xffffffffu, s0, o);
        q0 += __shfl_xor_sync(0xffffffffu, q0, o);
        s1 += __shfl_xor_sync(0xffffffffu, s1, o);
        q1 += __shfl_xor_sync(0xffffffffu, q1, o);
    }
    const float inv_h = 1.f / 128.f;
    float mu0 = s0 * inv_h, var0 = q0 * inv_h - mu0 * mu0;
    float mu1 = s1 * inv_h, var1 = q1 * inv_h - mu1 * mu1;
    float rs0 = rsqrtf(var0 + LN_EPS);
    float rs1 = rsqrtf(var1 + LN_EPS);
    const float inv_sqrt2 = 0.70710678118654752f;

#pragma unroll
    for (int nt = 0; nt < 16; nt++) {
        int col = nt * 8 + tig * 2;
        float2 gg = *(const float2*)(gamma + col);
        float2 be = *(const float2*)(beta + col);
        if (r0 < N_NODES) {
            float2 xv = *(const float2*)(x + (size_t)r0 * HIDDEN + col);
            float hn0 = (c[nt][0] - mu0) * rs0 * gg.x + be.x;
            float hn1 = (c[nt][1] - mu0) * rs0 * gg.y + be.y;
            float g0 = 0.5f * hn0 * (1.f + erff(hn0 * inv_sqrt2));
            float g1 = 0.5f * hn1 * (1.f + erff(hn1 * inv_sqrt2));
            *(float2*)(out + (size_t)r0 * HIDDEN + col) = make_float2(xv.x + g0, xv.y + g1);
        }
        if (r1 < N_NODES) {
            float2 xv = *(const float2*)(x + (size_t)r1 * HIDDEN + col);
            float hn2 = (c[nt][2] - mu1) * rs1 * gg.x + be.x;
            float hn3 = (c[nt][3] - mu1) * rs1 * gg.y + be.y;
            float g2 = 0.5f * hn2 * (1.f + erff(hn2 * inv_sqrt2));
            float g3 = 0.5f * hn3 * (1.f + erff(hn3 * inv_sqrt2));
            *(float2*)(out + (size_t)r1 * HIDDEN + col) = make_float2(xv.x + g2, xv.y + g3);
        }
    }
}

extern "C" void kernel_launch(void* const* d_in, const int* in_sizes, int n_in,
                              void* d_out, int out_size) {
    const float* x     = (const float*)d_in[0];
    const int*   ei    = (const int*)d_in[1];
    const int*   et    = (const int*)d_in[2];
    const float* Wmsg  = (const float*)d_in[3];
    const float* bmsg  = (const float*)d_in[4];
    const float* Wupd  = (const float*)d_in[5];
    const float* bupd  = (const float*)d_in[6];
    const float* gamma = (const float*)d_in[7];
    const float* beta  = (const float*)d_in[8];
    float* out = (float*)d_out;

    const int PROJ_SM = (128 * APAD + 2 * 64 * BPAD) * 4;   // 137216 B
    const int UPD_SM  = (128 * APAD + 128 * BPAD) * 4;      // 137216 B
    cudaFuncSetAttribute(k_proj,   cudaFuncAttributeMaxDynamicSharedMemorySize, PROJ_SM);
    cudaFuncSetAttribute(k_update, cudaFuncAttributeMaxDynamicSharedMemorySize, UPD_SM);

    k_prep<<<256, 256>>>(Wmsg, Wupd);                       // zero + both W transposes
    k_hist<<<(N_EDGES + 255) / 256, 256>>>(ei, et);

    k_proj<<<(N_NODES + 127) / 128, 512, PROJ_SM>>>(x, bmsg);

    k_scan1<<<SCAN_BLOCKS, 1024>>>();
    k_scan2<<<1, 1>>>();
    k_scan3<<<(N_NODES + 1023) / 1024, 1024>>>();
    k_fill<<<(N_EDGES + 255) / 256, 256>>>(ei, et);
    k_agg<<<(N_NODES + 7) / 8, 256>>>();

    k_update<<<(N_NODES + 127) / 128, 256, UPD_SM>>>(x, bupd, gamma, beta, out);
}